// round 11
// baseline (speedup 1.0000x reference)
#include <cuda_runtime.h>
#include <cuda_fp16.h>
#include <math.h>

#define BD    2
#define NSEQ  2048
#define CDIM  1024
#define RANK  64
#define HEADS 16
#define DH    64
#define MTOT  (BD*NSEQ)   // 4096
#define KDIM  1024

// Scratch (device globals: no allocation allowed in kernel_launch)
__device__ __half g_wah [2*KDIM*RANK];          // fp16 w_qkv_a | w_proj_a
__device__ __half g_hh  [MTOT*RANK];            // gelu(x @ w_qkv_a), fp16
__device__ __half g_h2h [MTOT*RANK];            // gelu(attn @ w_proj_a + b), fp16
__device__ __half g_qh  [BD*HEADS*NSEQ*DH];     // Q * 0.125*log2e, fp16 [bh][n][d]
__device__ __half g_kh  [BD*HEADS*NSEQ*DH];     // K fp16               [bh][n][d]
__device__ __half g_vTh [BD*HEADS*DH*NSEQ];     // V^T fp16             [bh][d][n]
__device__ __half g_attnh[MTOT*CDIM];           // attention out [B,N,C] fp16

__device__ __forceinline__ float gelu_exact(float v) {
    return 0.5f * v * (1.0f + erff(v * 0.70710678118654752440f));
}
__device__ __forceinline__ unsigned pack2(float a, float b) {
    __half2 h = __floats2half2_rn(a, b);
    return *(unsigned*)&h;
}
__device__ __forceinline__ void ldsm4(unsigned &r0, unsigned &r1, unsigned &r2, unsigned &r3, unsigned a) {
    asm volatile("ldmatrix.sync.aligned.m8n8.x4.shared.b16 {%0,%1,%2,%3}, [%4];"
                 : "=r"(r0),"=r"(r1),"=r"(r2),"=r"(r3) : "r"(a));
}
__device__ __forceinline__ void ldsm2(unsigned &r0, unsigned &r1, unsigned a) {
    asm volatile("ldmatrix.sync.aligned.m8n8.x2.shared.b16 {%0,%1}, [%2];"
                 : "=r"(r0),"=r"(r1) : "r"(a));
}
__device__ __forceinline__ void ldsm2t(unsigned &r0, unsigned &r1, unsigned a) {
    asm volatile("ldmatrix.sync.aligned.m8n8.x2.trans.shared.b16 {%0,%1}, [%2];"
                 : "=r"(r0),"=r"(r1) : "r"(a));
}
__device__ __forceinline__ void mma16(float* c, const unsigned* a, const unsigned* b) {
    asm volatile("mma.sync.aligned.m16n8k16.row.col.f32.f16.f16.f32 "
                 "{%0,%1,%2,%3},{%4,%5,%6,%7},{%8,%9},{%0,%1,%2,%3};"
                 : "+f"(c[0]),"+f"(c[1]),"+f"(c[2]),"+f"(c[3])
                 : "r"(a[0]),"r"(a[1]),"r"(a[2]),"r"(a[3]),"r"(b[0]),"r"(b[1]));
}
__device__ __forceinline__ void cp16(unsigned dst, const void* src) {
    asm volatile("cp.async.cg.shared.global [%0], [%1], 16;" :: "r"(dst), "l"(src));
}
__device__ __forceinline__ void cp_commit() { asm volatile("cp.async.commit_group;"); }
template<int N> __device__ __forceinline__ void cp_wait() {
    asm volatile("cp.async.wait_group %0;" :: "n"(N));
}

// ---------------------------------------------------------------------------
// One-shot weight converter: w_qkv_a, w_proj_a (fp32 [1024][64]) -> g_wah fp16.
// ---------------------------------------------------------------------------
__global__ __launch_bounds__(256) void convert_w_kernel(
    const float* __restrict__ wa, const float* __restrict__ wpa)
{
    int idx = blockIdx.x * 256 + threadIdx.x;
    float4 a = *(const float4*)&wa[idx * 4];
    float4 b = *(const float4*)&wpa[idx * 4];
    uint2 ua; ua.x = pack2(a.x, a.y); ua.y = pack2(a.z, a.w);
    uint2 ub; ub.x = pack2(b.x, b.y); ub.y = pack2(b.z, b.w);
    *(uint2*)&g_wah[idx * 4]               = ua;
    *(uint2*)&g_wah[KDIM*RANK + idx * 4]   = ub;
}

// ---------------------------------------------------------------------------
// out_fp16[M,64] = gelu(X[M,1024] @ W[1024,64] (+ bias)) via fp16 mma.
// X fp32 (XH=false) or fp16 (XH=true). 32-row tile, 64 threads (2 warps).
// ---------------------------------------------------------------------------
template<bool XH>
__global__ __launch_bounds__(64) void lowrank_a_mma_kernel(
    const float* __restrict__ Xf, const __half* __restrict__ Xh,
    const __half* __restrict__ Wh, const float* __restrict__ bias,
    __half* __restrict__ out)
{
    __shared__ __align__(16) __half Xs[32*72];
    __shared__ __align__(16) __half Ws[64*72];
    const int tid = threadIdx.x, lane = tid & 31, w = tid >> 5;
    const int m0 = blockIdx.x * 32;

    float4 xreg[8];
    uint4  xreg16[4];
    uint4  wreg[8];

    if (XH) {
        #pragma unroll
        for (int ii = 0; ii < 4; ii++) {
            int idx = tid + 64*ii, r = idx >> 3, c8 = (idx & 7) * 8;
            xreg16[ii] = *(const uint4*)&Xh[(m0 + r)*KDIM + c8];
        }
    } else {
        #pragma unroll
        for (int ii = 0; ii < 8; ii++) {
            int idx = tid + 64*ii, r = idx >> 4, c4 = (idx & 15) * 4;
            xreg[ii] = *(const float4*)&Xf[(m0 + r)*KDIM + c4];
        }
    }
    #pragma unroll
    for (int ii = 0; ii < 8; ii++) {
        int idx = tid + 64*ii, r = idx >> 3, c8 = (idx & 7) * 8;
        wreg[ii] = *(const uint4*)&Wh[r*RANK + c8];
    }

    const unsigned hA = (unsigned)__cvta_generic_to_shared(Xs)
                      + (unsigned)(((w*16 + (lane & 15))*72 + (lane >> 4)*8) * 2);
    const unsigned wB = (unsigned)__cvta_generic_to_shared(Ws)
                      + (unsigned)(((lane & 15)*72) * 2);

    float acc[8][4] = {};
    #pragma unroll 1
    for (int ch = 0; ch < KDIM/64; ch++) {
        if (XH) {
            #pragma unroll
            for (int ii = 0; ii < 4; ii++) {
                int idx = tid + 64*ii, r = idx >> 3, c8 = (idx & 7) * 8;
                *(uint4*)&Xs[r*72 + c8] = xreg16[ii];
            }
        } else {
            #pragma unroll
            for (int ii = 0; ii < 8; ii++) {
                int idx = tid + 64*ii, r = idx >> 4, c4 = (idx & 15) * 4;
                uint2 u; u.x = pack2(xreg[ii].x, xreg[ii].y);
                u.y = pack2(xreg[ii].z, xreg[ii].w);
                *(uint2*)&Xs[r*72 + c4] = u;
            }
        }
        #pragma unroll
        for (int ii = 0; ii < 8; ii++) {
            int idx = tid + 64*ii, r = idx >> 3, c8 = (idx & 7) * 8;
            *(uint4*)&Ws[r*72 + c8] = wreg[ii];
        }
        __syncthreads();
        if (ch + 1 < KDIM/64) {
            const int k0 = (ch + 1) * 64;
            if (XH) {
                #pragma unroll
                for (int ii = 0; ii < 4; ii++) {
                    int idx = tid + 64*ii, r = idx >> 3, c8 = (idx & 7) * 8;
                    xreg16[ii] = *(const uint4*)&Xh[(m0 + r)*KDIM + k0 + c8];
                }
            } else {
                #pragma unroll
                for (int ii = 0; ii < 8; ii++) {
                    int idx = tid + 64*ii, r = idx >> 4, c4 = (idx & 15) * 4;
                    xreg[ii] = *(const float4*)&Xf[(m0 + r)*KDIM + k0 + c4];
                }
            }
            #pragma unroll
            for (int ii = 0; ii < 8; ii++) {
                int idx = tid + 64*ii, r = idx >> 3, c8 = (idx & 7) * 8;
                wreg[ii] = *(const uint4*)&Wh[(k0 + r)*RANK + c8];
            }
        }
        #pragma unroll
        for (int ks = 0; ks < 4; ks++) {
            const int kk = ks * 16;
            unsigned af[4];
            ldsm4(af[0], af[1], af[2], af[3], hA + (unsigned)(kk * 2));
            #pragma unroll
            for (int j = 0; j < 8; j++) {
                unsigned bf[2];
                ldsm2t(bf[0], bf[1], wB + (unsigned)((kk*72 + j*8) * 2));
                mma16(acc[j], af, bf);
            }
        }
        __syncthreads();
    }

    const int rA = w*16 + (lane >> 2);
    #pragma unroll
    for (int j = 0; j < 8; j++) {
        int n = j*8 + (lane & 3)*2;
        float b0 = 0.f, b1 = 0.f;
        if (bias) { float2 bv = *(const float2*)&bias[n]; b0 = bv.x; b1 = bv.y; }
        *(unsigned*)&out[(m0 + rA    )*RANK + n] =
            pack2(gelu_exact(acc[j][0] + b0), gelu_exact(acc[j][1] + b1));
        *(unsigned*)&out[(m0 + rA + 8)*RANK + n] =
            pack2(gelu_exact(acc[j][2] + b0), gelu_exact(acc[j][3] + b1));
    }
}

// ---------------------------------------------------------------------------
// qkv = g_hh[4096,64] @ w_qkv_b[64,3072] via fp16 mma ->
//   g_qh (x 0.125*log2e), g_kh, g_vTh (transposed via SMEM staging).
// ---------------------------------------------------------------------------
__global__ __launch_bounds__(128) void expand_mma_kernel(const float* __restrict__ Wb)
{
    __shared__ __align__(16) __half Hs[64*72];
    __shared__ __align__(16) __half Wsm[64*136];
    const int tid = threadIdx.x, lane = tid & 31, w = tid >> 5;
    const int n0 = blockIdx.x * 128;
    const int m0 = blockIdx.y * 64;

    #pragma unroll
    for (int ii = 0; ii < 4; ii++) {
        int idx = tid + 128*ii, r = idx >> 3, c8 = (idx & 7) * 8;
        *(uint4*)&Hs[r*72 + c8] = *(const uint4*)&g_hh[(m0 + r)*64 + c8];
    }
    #pragma unroll
    for (int ii = 0; ii < 16; ii++) {
        int idx = tid + 128*ii, r = idx >> 5, c4 = (idx & 31) * 4;
        float4 v = *(const float4*)&Wb[r*(3*CDIM) + n0 + c4];
        uint2 u; u.x = pack2(v.x, v.y); u.y = pack2(v.z, v.w);
        *(uint2*)&Wsm[r*136 + c4] = u;
    }
    __syncthreads();

    const unsigned hA = (unsigned)__cvta_generic_to_shared(Hs)
                      + (unsigned)(((w*16 + (lane & 15))*72 + (lane >> 4)*8) * 2);
    const unsigned wB = (unsigned)__cvta_generic_to_shared(Wsm)
                      + (unsigned)(((lane & 15)*136) * 2);

    float acc[16][4] = {};
    #pragma unroll
    for (int ks = 0; ks < 4; ks++) {
        const int kk = ks * 16;
        unsigned af[4];
        ldsm4(af[0], af[1], af[2], af[3], hA + (unsigned)(kk * 2));
        #pragma unroll
        for (int j = 0; j < 16; j++) {
            unsigned bf[2];
            ldsm2t(bf[0], bf[1], wB + (unsigned)((kk*136 + j*8) * 2));
            mma16(acc[j], af, bf);
        }
    }

    const int comp = n0 >> 10;
    const int bb   = m0 >> 11;
    const int ns0  = m0 & 2047;
    const int rA   = w*16 + (lane >> 2);

    if (comp < 2) {
        const float sc = (comp == 0) ? (0.125f * 1.44269504088896341f) : 1.0f;
        __half* dst = (comp == 0) ? g_qh : g_kh;
        #pragma unroll
        for (int j = 0; j < 16; j++) {
            int gn   = (n0 + j*8 + (lane & 3)*2) & 1023;
            int head = gn >> 6, d = gn & 63;
            size_t base = ((size_t)(bb*HEADS + head)*NSEQ + ns0);
            *(unsigned*)&dst[(base + rA    )*DH + d] = pack2(acc[j][0]*sc, acc[j][1]*sc);
            *(unsigned*)&dst[(base + rA + 8)*DH + d] = pack2(acc[j][2]*sc, acc[j][3]*sc);
        }
    } else {
        __syncthreads();
        __half* Ts = Hs;
        #pragma unroll
        for (int j = 0; j < 16; j++) {
            int c = j*8 + (lane & 3)*2;
            Ts[(c+0)*72 + rA    ] = __float2half(acc[j][0]);
            Ts[(c+1)*72 + rA    ] = __float2half(acc[j][1]);
            Ts[(c+0)*72 + rA + 8] = __float2half(acc[j][2]);
            Ts[(c+1)*72 + rA + 8] = __float2half(acc[j][3]);
        }
        __syncthreads();
        int c    = tid;
        int gn   = (n0 + c) & 1023;
        int head = gn >> 6, d = gn & 63;
        size_t base = ((size_t)(bb*HEADS + head)*DH + d)*NSEQ + ns0;
        #pragma unroll
        for (int g = 0; g < 8; g++)
            *(uint4*)&g_vTh[base + g*8] = *(uint4*)&Ts[c*72 + g*8];
    }
}

// ---------------------------------------------------------------------------
// y[4096,1024] = g_h2h[4096,64] @ w_proj_b[64,1024] + b_proj_b   (fp16 mma)
// ---------------------------------------------------------------------------
__global__ __launch_bounds__(128) void lowrank_out_mma_kernel(
    const float* __restrict__ Wb, const float* __restrict__ bias,
    float* __restrict__ out)
{
    __shared__ __align__(16) __half Hs[64*72];
    __shared__ __align__(16) __half Wsm[64*136];
    const int tid = threadIdx.x, lane = tid & 31, w = tid >> 5;
    const int n0 = blockIdx.x * 128;
    const int m0 = blockIdx.y * 64;

    #pragma unroll
    for (int ii = 0; ii < 4; ii++) {
        int idx = tid + 128*ii, r = idx >> 3, c8 = (idx & 7) * 8;
        *(uint4*)&Hs[r*72 + c8] = *(const uint4*)&g_h2h[(m0 + r)*64 + c8];
    }
    #pragma unroll
    for (int ii = 0; ii < 16; ii++) {
        int idx = tid + 128*ii, r = idx >> 5, c4 = (idx & 31) * 4;
        float4 v = *(const float4*)&Wb[r*CDIM + n0 + c4];
        uint2 u; u.x = pack2(v.x, v.y); u.y = pack2(v.z, v.w);
        *(uint2*)&Wsm[r*136 + c4] = u;
    }
    __syncthreads();

    const unsigned hA = (unsigned)__cvta_generic_to_shared(Hs)
                      + (unsigned)(((w*16 + (lane & 15))*72 + (lane >> 4)*8) * 2);
    const unsigned wB = (unsigned)__cvta_generic_to_shared(Wsm)
                      + (unsigned)(((lane & 15)*136) * 2);

    float acc[16][4] = {};
    #pragma unroll
    for (int ks = 0; ks < 4; ks++) {
        const int kk = ks * 16;
        unsigned af[4];
        ldsm4(af[0], af[1], af[2], af[3], hA + (unsigned)(kk * 2));
        #pragma unroll
        for (int j = 0; j < 16; j++) {
            unsigned bf[2];
            ldsm2t(bf[0], bf[1], wB + (unsigned)((kk*136 + j*8) * 2));
            mma16(acc[j], af, bf);
        }
    }

    const int rA = w*16 + (lane >> 2);
    #pragma unroll
    for (int j = 0; j < 16; j++) {
        int n = n0 + j*8 + (lane & 3)*2;
        float2 bv = *(const float2*)&bias[n];
        size_t b0 = (size_t)(m0 + rA    )*CDIM + n;
        size_t b1 = (size_t)(m0 + rA + 8)*CDIM + n;
        *(float2*)&out[b0] = make_float2(acc[j][0] + bv.x, acc[j][1] + bv.y);
        *(float2*)&out[b1] = make_float2(acc[j][2] + bv.x, acc[j][3] + bv.y);
    }
}

// ---------------------------------------------------------------------------
// Flash attention, fp16 mma.m16n8k16, fp32 accum, exp2-domain softmax.
// Grid (NSEQ/128, B*H), 256 threads (8 warps), warp w owns q-rows [16w,16w+16).
// KV tile 64, 2-stage cp.async. P in registers. Deferred l-reduction:
// per-thread partial row sums, quad-reduced only in the epilogue.
// ---------------------------------------------------------------------------
#define LDH 72
#define FLASH_SMEM ((128 + 4*64) * LDH * 2)

__global__ __launch_bounds__(256) void flash_mma_kernel()
{
    extern __shared__ __align__(16) __half smh[];
    __half* Qs = smh;                                 // [128][LDH]

    const int tid  = threadIdx.x;
    const int lane = tid & 31, w = tid >> 5;          // 8 warps
    const int bh = blockIdx.y;
    const int q0 = blockIdx.x * 128;
    const int b = bh >> 4, h = bh & 15;

    const __half* Qg  = g_qh  + ((size_t)bh * NSEQ + q0) * DH;
    const __half* Kg  = g_kh  + (size_t)bh * NSEQ * DH;
    const __half* VTg = g_vTh + (size_t)bh * DH * NSEQ;

    const unsigned sbase = (unsigned)__cvta_generic_to_shared(smh);

    // prologue: async-load KV tile 0 into buf 0 (256 threads, 2 iters per tile)
    {
        unsigned kdst = sbase + (unsigned)(128*LDH*2);
        unsigned vdst = kdst + (unsigned)(64*LDH*2);
        #pragma unroll
        for (int it = 0; it < 2; it++) {
            int i = tid + 256*it, r = i >> 3, c8 = (i & 7)*8;
            cp16(kdst + (unsigned)((r*LDH + c8)*2), &Kg[r*DH + c8]);
            cp16(vdst + (unsigned)((r*LDH + c8)*2), &VTg[(size_t)r*NSEQ + c8]);
        }
        cp_commit();
    }
    #pragma unroll
    for (int it = 0; it < 4; it++) {
        int i = tid + 256 * it, r = i >> 3, c8 = (i & 7) * 8;
        *(uint4*)&Qs[r*LDH + c8] = *(const uint4*)&Qg[r*DH + c8];
    }

    const unsigned aOff = (unsigned)((((lane & 15) * LDH) + (lane >> 4) * 8) * 2);
    const unsigned bOff = (unsigned)((((lane & 7) * LDH) + ((lane >> 3) & 1) * 8) * 2);
    const unsigned qsA = sbase + aOff + (unsigned)(w*16*LDH*2);

    float o[8][4];
    float mrow[2], lrow[2];        // lrow = per-thread PARTIAL row sum
    mrow[0] = mrow[1] = -1e30f;
    lrow[0] = lrow[1] = 0.f;
    #pragma unroll
    for (int j = 0; j < 8; j++)
        o[j][0] = o[j][1] = o[j][2] = o[j][3] = 0.f;

    for (int t = 0; t < NSEQ/64; t++) {
        if (t + 1 < NSEQ/64) {
            const __half* Kt = Kg + (size_t)(t+1) * 64 * DH;
            unsigned kdst = sbase + (unsigned)((128 + ((t+1)&1)*128)*LDH*2);
            unsigned vdst = kdst + (unsigned)(64*LDH*2);
            #pragma unroll
            for (int it = 0; it < 2; it++) {
                int i = tid + 256*it, r = i >> 3, c8 = (i & 7)*8;
                cp16(kdst + (unsigned)((r*LDH + c8)*2), &Kt[r*DH + c8]);
                cp16(vdst + (unsigned)((r*LDH + c8)*2), &VTg[(size_t)r*NSEQ + (t+1)*64 + c8]);
            }
            cp_commit();
            cp_wait<1>();
        } else {
            cp_wait<0>();
        }
        __syncthreads();

        const unsigned kB = sbase + (unsigned)((128 + (t&1)*128)*LDH*2) + bOff;
        const unsigned vB = kB + (unsigned)(64*LDH*2);

        // ---- S = Q K^T  (1 m-tile x 8 n-tiles x 4 k-steps) ----
        float s[8][4];
        #pragma unroll
        for (int j = 0; j < 8; j++)
            s[j][0] = s[j][1] = s[j][2] = s[j][3] = 0.f;

        #pragma unroll
        for (int ks = 0; ks < 4; ks++) {
            const int kk = ks * 16;
            unsigned af[4];
            ldsm4(af[0], af[1], af[2], af[3], qsA + (unsigned)(kk * 2));
            #pragma unroll
            for (int j = 0; j < 8; j++) {
                unsigned bf[2];
                ldsm2(bf[0], bf[1], kB + (unsigned)((j*8*LDH + kk) * 2));
                mma16(s[j], af, bf);
            }
        }

        // ---- online softmax (log2 domain) ----
        unsigned pp[8][2];
        {
            float mxl = -1e30f, mxh = -1e30f;
            #pragma unroll
            for (int j = 0; j < 8; j++) {
                mxl = fmaxf(mxl, fmaxf(s[j][0], s[j][1]));
                mxh = fmaxf(mxh, fmaxf(s[j][2], s[j][3]));
            }
            mxl = fmaxf(mxl, __shfl_xor_sync(0xffffffffu, mxl, 1));
            mxl = fmaxf(mxl, __shfl_xor_sync(0xffffffffu, mxl, 2));
            mxh = fmaxf(mxh, __shfl_xor_sync(0xffffffffu, mxh, 1));
            mxh = fmaxf(mxh, __shfl_xor_sync(0xffffffffu, mxh, 2));
            float mln = fmaxf(mrow[0], mxl);
            float mhn = fmaxf(mrow[1], mxh);
            float al = exp2f(mrow[0] - mln);
            float ah = exp2f(mrow[1] - mhn);
            bool resc = (mln > mrow[0]) | (mhn > mrow[1]);
            mrow[0] = mln; mrow[1] = mhn;
            float sl = 0.f, sh = 0.f;
            #pragma unroll
            for (int j = 0; j < 8; j++) {
                __half2 hl = __floats2half2_rn(exp2f(s[j][0] - mln),
                                               exp2f(s[j][1] - mln));
                __half2 hh = __floats2half2_rn(exp2f(s[j][2] - mhn),
                                               exp2f(s[j][3] - mhn));
                float2 fl = __half22float2(hl), fh = __half22float2(hh);
                sl += fl.x + fl.y; sh += fh.x + fh.y;
                pp[j][0] = *(unsigned*)&hl;
                pp[j][1] = *(unsigned*)&hh;
            }
            // deferred: lrow is a per-thread partial (quad threads share al/ah)
            if (__any_sync(0xffffffffu, resc)) {
                lrow[0] = lrow[0]*al + sl;
                lrow[1] = lrow[1]*ah + sh;
                #pragma unroll
                for (int j = 0; j < 8; j++) {
                    o[j][0] *= al; o[j][1] *= al;
                    o[j][2] *= ah; o[j][3] *= ah;
                }
            } else {
                lrow[0] += sl;
                lrow[1] += sh;
            }
        }

        // ---- O += P V ----
        #pragma unroll
        for (int ks = 0; ks < 4; ks++) {
            const int kc = ks * 16;
            unsigned af[4] = { pp[2*ks][0], pp[2*ks][1],
                               pp[2*ks+1][0], pp[2*ks+1][1] };
            #pragma unroll
            for (int jd = 0; jd < 8; jd++) {
                unsigned bf[2];
                ldsm2(bf[0], bf[1], vB + (unsigned)((jd*8*LDH + kc) * 2));
                mma16(o[jd], af, bf);
            }
        }
        __syncthreads();
    }

    // ---- epilogue: quad-reduce partial sums, fp16 out to g_attnh ----
    lrow[0] += __shfl_xor_sync(0xffffffffu, lrow[0], 1);
    lrow[0] += __shfl_xor_sync(0xffffffffu, lrow[0], 2);
    lrow[1] += __shfl_xor_sync(0xffffffffu, lrow[1], 1);
    lrow[1] += __shfl_xor_sync(0xffffffffu, lrow[1], 2);
    float il = 1.0f / lrow[0], ih = 1.0f / lrow[1];
    int rowl = q0 + w*16 + (lane >> 2);
    size_t basel = ((size_t)(b*NSEQ + rowl))*CDIM + h*DH + (lane & 3)*2;
    size_t baseh = basel + (size_t)8*CDIM;
    #pragma unroll
    for (int j = 0; j < 8; j++) {
        *(unsigned*)&g_attnh[basel + j*8] = pack2(o[j][0]*il, o[j][1]*il);
        *(unsigned*)&g_attnh[baseh + j*8] = pack2(o[j][2]*ih, o[j][3]*ih);
    }
}

// ---------------------------------------------------------------------------
extern "C" void kernel_launch(void* const* d_in, const int* in_sizes, int n_in,
                              void* d_out, int out_size)
{
    const float* x        = (const float*)d_in[0];
    const float* w_qkv_a  = (const float*)d_in[1];
    const float* w_qkv_b  = (const float*)d_in[2];
    const float* w_proj_a = (const float*)d_in[3];
    const float* b_proj_a = (const float*)d_in[4];
    const float* w_proj_b = (const float*)d_in[5];
    const float* b_proj_b = (const float*)d_in[6];
    float* out = (float*)d_out;

    __half *pwah = nullptr, *phh = nullptr, *ph2h = nullptr, *pattnh = nullptr;
    cudaGetSymbolAddress((void**)&pwah,   g_wah);
    cudaGetSymbolAddress((void**)&phh,    g_hh);
    cudaGetSymbolAddress((void**)&ph2h,   g_h2h);
    cudaGetSymbolAddress((void**)&pattnh, g_attnh);

    static bool attr_set = false;
    if (!attr_set) {
        cudaFuncSetAttribute(flash_mma_kernel,
                             cudaFuncAttributeMaxDynamicSharedMemorySize, FLASH_SMEM);
        attr_set = true;
    }

    // 0. fp16 weight staging for the two K=1024 "A" GEMMs
    convert_w_kernel<<<64, 256>>>(w_qkv_a, w_proj_a);
    // 1. h = gelu(x @ w_qkv_a)                 fp16 [4096,64]
    lowrank_a_mma_kernel<false><<<MTOT/32, 64>>>(x, nullptr, pwah, nullptr, phh);
    // 2. qkv = h @ w_qkv_b (mma) -> q (x0.125*log2e), k, vT  (fp16)
    expand_mma_kernel<<<dim3(3*CDIM/128, MTOT/64), 128>>>(w_qkv_b);
    // 3. fp16 tensor-core flash attention -> g_attnh [B,N,C] fp16
    flash_mma_kernel<<<dim3(NSEQ/128, BD*HEADS), 256, FLASH_SMEM>>>();
    // 4. h2 = gelu(attn @ w_proj_a + b_proj_a) fp16 [4096,64]
    lowrank_a_mma_kernel<true><<<MTOT/32, 64>>>(nullptr, pattnh, pwah + KDIM*RANK,
                                                b_proj_a, ph2h);
    // 5. y = h2 @ w_proj_b + b_proj_b (mma)    fp32 [4096,1024]
    lowrank_out_mma_kernel<<<dim3(CDIM/128, MTOT/64), 128>>>(w_proj_b, b_proj_b, out);
}

// round 12
// speedup vs baseline: 1.0657x; 1.0657x over previous
#include <cuda_runtime.h>
#include <cuda_fp16.h>
#include <math.h>

#define BD    2
#define NSEQ  2048
#define CDIM  1024
#define RANK  64
#define HEADS 16
#define DH    64
#define MTOT  (BD*NSEQ)   // 4096
#define KDIM  1024

// Scratch (device globals: no allocation allowed in kernel_launch)
__device__ __half g_wah [2*KDIM*RANK];          // fp16 w_qkv_a | w_proj_a
__device__ __half g_hh  [MTOT*RANK];            // gelu(x @ w_qkv_a), fp16
__device__ __half g_h2h [MTOT*RANK];            // gelu(attn @ w_proj_a + b), fp16
__device__ __half g_qh  [BD*HEADS*NSEQ*DH];     // Q * 0.125*log2e, fp16 [bh][n][d]
__device__ __half g_kh  [BD*HEADS*NSEQ*DH];     // K fp16               [bh][n][d]
__device__ __half g_vTh [BD*HEADS*DH*NSEQ];     // V^T fp16             [bh][d][n]
__device__ __half g_attnh[MTOT*CDIM];           // attention out [B,N,C] fp16

__device__ __forceinline__ float gelu_exact(float v) {
    return 0.5f * v * (1.0f + erff(v * 0.70710678118654752440f));
}
__device__ __forceinline__ unsigned pack2(float a, float b) {
    __half2 h = __floats2half2_rn(a, b);
    return *(unsigned*)&h;
}
__device__ __forceinline__ void ldsm4(unsigned &r0, unsigned &r1, unsigned &r2, unsigned &r3, unsigned a) {
    asm volatile("ldmatrix.sync.aligned.m8n8.x4.shared.b16 {%0,%1,%2,%3}, [%4];"
                 : "=r"(r0),"=r"(r1),"=r"(r2),"=r"(r3) : "r"(a));
}
__device__ __forceinline__ void ldsm2(unsigned &r0, unsigned &r1, unsigned a) {
    asm volatile("ldmatrix.sync.aligned.m8n8.x2.shared.b16 {%0,%1}, [%2];"
                 : "=r"(r0),"=r"(r1) : "r"(a));
}
__device__ __forceinline__ void ldsm2t(unsigned &r0, unsigned &r1, unsigned a) {
    asm volatile("ldmatrix.sync.aligned.m8n8.x2.trans.shared.b16 {%0,%1}, [%2];"
                 : "=r"(r0),"=r"(r1) : "r"(a));
}
__device__ __forceinline__ void mma16(float* c, const unsigned* a, const unsigned* b) {
    asm volatile("mma.sync.aligned.m16n8k16.row.col.f32.f16.f16.f32 "
                 "{%0,%1,%2,%3},{%4,%5,%6,%7},{%8,%9},{%0,%1,%2,%3};"
                 : "+f"(c[0]),"+f"(c[1]),"+f"(c[2]),"+f"(c[3])
                 : "r"(a[0]),"r"(a[1]),"r"(a[2]),"r"(a[3]),"r"(b[0]),"r"(b[1]));
}
__device__ __forceinline__ void cp16(unsigned dst, const void* src) {
    asm volatile("cp.async.cg.shared.global [%0], [%1], 16;" :: "r"(dst), "l"(src));
}
__device__ __forceinline__ void cp_commit() { asm volatile("cp.async.commit_group;"); }
template<int N> __device__ __forceinline__ void cp_wait() {
    asm volatile("cp.async.wait_group %0;" :: "n"(N));
}

// ---------------------------------------------------------------------------
// One-shot weight converter: w_qkv_a, w_proj_a (fp32 [1024][64]) -> g_wah fp16.
// ---------------------------------------------------------------------------
__global__ __launch_bounds__(256) void convert_w_kernel(
    const float* __restrict__ wa, const float* __restrict__ wpa)
{
    int idx = blockIdx.x * 256 + threadIdx.x;
    float4 a = *(const float4*)&wa[idx * 4];
    float4 b = *(const float4*)&wpa[idx * 4];
    uint2 ua; ua.x = pack2(a.x, a.y); ua.y = pack2(a.z, a.w);
    uint2 ub; ub.x = pack2(b.x, b.y); ub.y = pack2(b.z, b.w);
    *(uint2*)&g_wah[idx * 4]               = ua;
    *(uint2*)&g_wah[KDIM*RANK + idx * 4]   = ub;
}

// ---------------------------------------------------------------------------
// out_fp16[M,64] = gelu(X[M,1024] @ W[1024,64] (+ bias)) via fp16 mma.
// X fp32 (XH=false) or fp16 (XH=true). 32-row tile, 64 threads (2 warps).
// ---------------------------------------------------------------------------
template<bool XH>
__global__ __launch_bounds__(64) void lowrank_a_mma_kernel(
    const float* __restrict__ Xf, const __half* __restrict__ Xh,
    const __half* __restrict__ Wh, const float* __restrict__ bias,
    __half* __restrict__ out)
{
    __shared__ __align__(16) __half Xs[32*72];
    __shared__ __align__(16) __half Ws[64*72];
    const int tid = threadIdx.x, lane = tid & 31, w = tid >> 5;
    const int m0 = blockIdx.x * 32;

    float4 xreg[8];
    uint4  xreg16[4];
    uint4  wreg[8];

    if (XH) {
        #pragma unroll
        for (int ii = 0; ii < 4; ii++) {
            int idx = tid + 64*ii, r = idx >> 3, c8 = (idx & 7) * 8;
            xreg16[ii] = *(const uint4*)&Xh[(m0 + r)*KDIM + c8];
        }
    } else {
        #pragma unroll
        for (int ii = 0; ii < 8; ii++) {
            int idx = tid + 64*ii, r = idx >> 4, c4 = (idx & 15) * 4;
            xreg[ii] = *(const float4*)&Xf[(m0 + r)*KDIM + c4];
        }
    }
    #pragma unroll
    for (int ii = 0; ii < 8; ii++) {
        int idx = tid + 64*ii, r = idx >> 3, c8 = (idx & 7) * 8;
        wreg[ii] = *(const uint4*)&Wh[r*RANK + c8];
    }

    const unsigned hA = (unsigned)__cvta_generic_to_shared(Xs)
                      + (unsigned)(((w*16 + (lane & 15))*72 + (lane >> 4)*8) * 2);
    const unsigned wB = (unsigned)__cvta_generic_to_shared(Ws)
                      + (unsigned)(((lane & 15)*72) * 2);

    float acc[8][4] = {};
    #pragma unroll 1
    for (int ch = 0; ch < KDIM/64; ch++) {
        if (XH) {
            #pragma unroll
            for (int ii = 0; ii < 4; ii++) {
                int idx = tid + 64*ii, r = idx >> 3, c8 = (idx & 7) * 8;
                *(uint4*)&Xs[r*72 + c8] = xreg16[ii];
            }
        } else {
            #pragma unroll
            for (int ii = 0; ii < 8; ii++) {
                int idx = tid + 64*ii, r = idx >> 4, c4 = (idx & 15) * 4;
                uint2 u; u.x = pack2(xreg[ii].x, xreg[ii].y);
                u.y = pack2(xreg[ii].z, xreg[ii].w);
                *(uint2*)&Xs[r*72 + c4] = u;
            }
        }
        #pragma unroll
        for (int ii = 0; ii < 8; ii++) {
            int idx = tid + 64*ii, r = idx >> 3, c8 = (idx & 7) * 8;
            *(uint4*)&Ws[r*72 + c8] = wreg[ii];
        }
        __syncthreads();
        if (ch + 1 < KDIM/64) {
            const int k0 = (ch + 1) * 64;
            if (XH) {
                #pragma unroll
                for (int ii = 0; ii < 4; ii++) {
                    int idx = tid + 64*ii, r = idx >> 3, c8 = (idx & 7) * 8;
                    xreg16[ii] = *(const uint4*)&Xh[(m0 + r)*KDIM + k0 + c8];
                }
            } else {
                #pragma unroll
                for (int ii = 0; ii < 8; ii++) {
                    int idx = tid + 64*ii, r = idx >> 4, c4 = (idx & 15) * 4;
                    xreg[ii] = *(const float4*)&Xf[(m0 + r)*KDIM + k0 + c4];
                }
            }
            #pragma unroll
            for (int ii = 0; ii < 8; ii++) {
                int idx = tid + 64*ii, r = idx >> 3, c8 = (idx & 7) * 8;
                wreg[ii] = *(const uint4*)&Wh[(k0 + r)*RANK + c8];
            }
        }
        #pragma unroll
        for (int ks = 0; ks < 4; ks++) {
            const int kk = ks * 16;
            unsigned af[4];
            ldsm4(af[0], af[1], af[2], af[3], hA + (unsigned)(kk * 2));
            #pragma unroll
            for (int j = 0; j < 8; j++) {
                unsigned bf[2];
                ldsm2t(bf[0], bf[1], wB + (unsigned)((kk*72 + j*8) * 2));
                mma16(acc[j], af, bf);
            }
        }
        __syncthreads();
    }

    const int rA = w*16 + (lane >> 2);
    #pragma unroll
    for (int j = 0; j < 8; j++) {
        int n = j*8 + (lane & 3)*2;
        float b0 = 0.f, b1 = 0.f;
        if (bias) { float2 bv = *(const float2*)&bias[n]; b0 = bv.x; b1 = bv.y; }
        *(unsigned*)&out[(m0 + rA    )*RANK + n] =
            pack2(gelu_exact(acc[j][0] + b0), gelu_exact(acc[j][1] + b1));
        *(unsigned*)&out[(m0 + rA + 8)*RANK + n] =
            pack2(gelu_exact(acc[j][2] + b0), gelu_exact(acc[j][3] + b1));
    }
}

// ---------------------------------------------------------------------------
// qkv = g_hh[4096,64] @ w_qkv_b[64,3072] via fp16 mma ->
//   g_qh (x 0.125*log2e), g_kh, g_vTh (transposed via SMEM staging).
// ---------------------------------------------------------------------------
__global__ __launch_bounds__(128) void expand_mma_kernel(const float* __restrict__ Wb)
{
    __shared__ __align__(16) __half Hs[64*72];
    __shared__ __align__(16) __half Wsm[64*136];
    const int tid = threadIdx.x, lane = tid & 31, w = tid >> 5;
    const int n0 = blockIdx.x * 128;
    const int m0 = blockIdx.y * 64;

    #pragma unroll
    for (int ii = 0; ii < 4; ii++) {
        int idx = tid + 128*ii, r = idx >> 3, c8 = (idx & 7) * 8;
        *(uint4*)&Hs[r*72 + c8] = *(const uint4*)&g_hh[(m0 + r)*64 + c8];
    }
    #pragma unroll
    for (int ii = 0; ii < 16; ii++) {
        int idx = tid + 128*ii, r = idx >> 5, c4 = (idx & 31) * 4;
        float4 v = *(const float4*)&Wb[r*(3*CDIM) + n0 + c4];
        uint2 u; u.x = pack2(v.x, v.y); u.y = pack2(v.z, v.w);
        *(uint2*)&Wsm[r*136 + c4] = u;
    }
    __syncthreads();

    const unsigned hA = (unsigned)__cvta_generic_to_shared(Hs)
                      + (unsigned)(((w*16 + (lane & 15))*72 + (lane >> 4)*8) * 2);
    const unsigned wB = (unsigned)__cvta_generic_to_shared(Wsm)
                      + (unsigned)(((lane & 15)*136) * 2);

    float acc[16][4] = {};
    #pragma unroll
    for (int ks = 0; ks < 4; ks++) {
        const int kk = ks * 16;
        unsigned af[4];
        ldsm4(af[0], af[1], af[2], af[3], hA + (unsigned)(kk * 2));
        #pragma unroll
        for (int j = 0; j < 16; j++) {
            unsigned bf[2];
            ldsm2t(bf[0], bf[1], wB + (unsigned)((kk*136 + j*8) * 2));
            mma16(acc[j], af, bf);
        }
    }

    const int comp = n0 >> 10;
    const int bb   = m0 >> 11;
    const int ns0  = m0 & 2047;
    const int rA   = w*16 + (lane >> 2);

    if (comp < 2) {
        const float sc = (comp == 0) ? (0.125f * 1.44269504088896341f) : 1.0f;
        __half* dst = (comp == 0) ? g_qh : g_kh;
        #pragma unroll
        for (int j = 0; j < 16; j++) {
            int gn   = (n0 + j*8 + (lane & 3)*2) & 1023;
            int head = gn >> 6, d = gn & 63;
            size_t base = ((size_t)(bb*HEADS + head)*NSEQ + ns0);
            *(unsigned*)&dst[(base + rA    )*DH + d] = pack2(acc[j][0]*sc, acc[j][1]*sc);
            *(unsigned*)&dst[(base + rA + 8)*DH + d] = pack2(acc[j][2]*sc, acc[j][3]*sc);
        }
    } else {
        __syncthreads();
        __half* Ts = Hs;
        #pragma unroll
        for (int j = 0; j < 16; j++) {
            int c = j*8 + (lane & 3)*2;
            Ts[(c+0)*72 + rA    ] = __float2half(acc[j][0]);
            Ts[(c+1)*72 + rA    ] = __float2half(acc[j][1]);
            Ts[(c+0)*72 + rA + 8] = __float2half(acc[j][2]);
            Ts[(c+1)*72 + rA + 8] = __float2half(acc[j][3]);
        }
        __syncthreads();
        int c    = tid;
        int gn   = (n0 + c) & 1023;
        int head = gn >> 6, d = gn & 63;
        size_t base = ((size_t)(bb*HEADS + head)*DH + d)*NSEQ + ns0;
        #pragma unroll
        for (int g = 0; g < 8; g++)
            *(uint4*)&g_vTh[base + g*8] = *(uint4*)&Ts[c*72 + g*8];
    }
}

// ---------------------------------------------------------------------------
// y[4096,1024] = g_h2h[4096,64] @ w_proj_b[64,1024] + b_proj_b   (fp16 mma)
// ---------------------------------------------------------------------------
__global__ __launch_bounds__(128) void lowrank_out_mma_kernel(
    const float* __restrict__ Wb, const float* __restrict__ bias,
    float* __restrict__ out)
{
    __shared__ __align__(16) __half Hs[64*72];
    __shared__ __align__(16) __half Wsm[64*136];
    const int tid = threadIdx.x, lane = tid & 31, w = tid >> 5;
    const int n0 = blockIdx.x * 128;
    const int m0 = blockIdx.y * 64;

    #pragma unroll
    for (int ii = 0; ii < 4; ii++) {
        int idx = tid + 128*ii, r = idx >> 3, c8 = (idx & 7) * 8;
        *(uint4*)&Hs[r*72 + c8] = *(const uint4*)&g_h2h[(m0 + r)*64 + c8];
    }
    #pragma unroll
    for (int ii = 0; ii < 16; ii++) {
        int idx = tid + 128*ii, r = idx >> 5, c4 = (idx & 31) * 4;
        float4 v = *(const float4*)&Wb[r*CDIM + n0 + c4];
        uint2 u; u.x = pack2(v.x, v.y); u.y = pack2(v.z, v.w);
        *(uint2*)&Wsm[r*136 + c4] = u;
    }
    __syncthreads();

    const unsigned hA = (unsigned)__cvta_generic_to_shared(Hs)
                      + (unsigned)(((w*16 + (lane & 15))*72 + (lane >> 4)*8) * 2);
    const unsigned wB = (unsigned)__cvta_generic_to_shared(Wsm)
                      + (unsigned)(((lane & 15)*136) * 2);

    float acc[16][4] = {};
    #pragma unroll
    for (int ks = 0; ks < 4; ks++) {
        const int kk = ks * 16;
        unsigned af[4];
        ldsm4(af[0], af[1], af[2], af[3], hA + (unsigned)(kk * 2));
        #pragma unroll
        for (int j = 0; j < 16; j++) {
            unsigned bf[2];
            ldsm2t(bf[0], bf[1], wB + (unsigned)((kk*136 + j*8) * 2));
            mma16(acc[j], af, bf);
        }
    }

    const int rA = w*16 + (lane >> 2);
    #pragma unroll
    for (int j = 0; j < 16; j++) {
        int n = n0 + j*8 + (lane & 3)*2;
        float2 bv = *(const float2*)&bias[n];
        size_t b0 = (size_t)(m0 + rA    )*CDIM + n;
        size_t b1 = (size_t)(m0 + rA + 8)*CDIM + n;
        *(float2*)&out[b0] = make_float2(acc[j][0] + bv.x, acc[j][1] + bv.y);
        *(float2*)&out[b1] = make_float2(acc[j][2] + bv.x, acc[j][3] + bv.y);
    }
}

// ---------------------------------------------------------------------------
// Flash attention, fp16 mma.m16n8k16, fp32 accum, exp2-domain softmax.
// Grid (NSEQ/128, B*H), 128 threads (4 warps), warp w owns q-rows [32w,32w+32).
// KV tile 64, 2-stage cp.async. Q fragments hoisted to registers.
// P in registers. Deferred l-reduction + conditional O rescale.
// ---------------------------------------------------------------------------
#define LDH 72
#define FLASH_SMEM ((128 + 4*64) * LDH * 2)

__global__ __launch_bounds__(128) void flash_mma_kernel()
{
    extern __shared__ __align__(16) __half smh[];
    __half* Qs = smh;                                 // [128][LDH]

    const int tid  = threadIdx.x;
    const int lane = tid & 31, w = tid >> 5;
    const int bh = blockIdx.y;
    const int q0 = blockIdx.x * 128;
    const int b = bh >> 4, h = bh & 15;

    const __half* Qg  = g_qh  + ((size_t)bh * NSEQ + q0) * DH;
    const __half* Kg  = g_kh  + (size_t)bh * NSEQ * DH;
    const __half* VTg = g_vTh + (size_t)bh * DH * NSEQ;

    const unsigned sbase = (unsigned)__cvta_generic_to_shared(smh);

    // prologue: async-load KV tile 0 into buf 0
    {
        unsigned kdst = sbase + (unsigned)(128*LDH*2);
        unsigned vdst = kdst + (unsigned)(64*LDH*2);
        #pragma unroll
        for (int it = 0; it < 4; it++) {
            int i = tid + 128*it, r = i >> 3, c8 = (i & 7)*8;
            cp16(kdst + (unsigned)((r*LDH + c8)*2), &Kg[r*DH + c8]);
            cp16(vdst + (unsigned)((r*LDH + c8)*2), &VTg[(size_t)r*NSEQ + c8]);
        }
        cp_commit();
    }
    // Q tile to SMEM, then hoist fragments to registers
    #pragma unroll
    for (int it = 0; it < 8; it++) {
        int i = tid + 128 * it, r = i >> 3, c8 = (i & 7) * 8;
        *(uint4*)&Qs[r*LDH + c8] = *(const uint4*)&Qg[r*DH + c8];
    }
    __syncthreads();

    const unsigned aOff = (unsigned)((((lane & 15) * LDH) + (lane >> 4) * 8) * 2);
    const unsigned bOff = (unsigned)((((lane & 7) * LDH) + ((lane >> 3) & 1) * 8) * 2);

    unsigned qf[2][4][4];      // [m-tile][k-step][frag]
    #pragma unroll
    for (int mt = 0; mt < 2; mt++)
        #pragma unroll
        for (int ks = 0; ks < 4; ks++)
            ldsm4(qf[mt][ks][0], qf[mt][ks][1], qf[mt][ks][2], qf[mt][ks][3],
                  sbase + aOff + (unsigned)(((w*32 + mt*16)*LDH + ks*16) * 2));

    float o[2][8][4];
    float mrow[2][2], lrow[2][2];     // lrow = per-thread PARTIAL row sums
    #pragma unroll
    for (int mt = 0; mt < 2; mt++) {
        mrow[mt][0] = mrow[mt][1] = -1e30f;
        lrow[mt][0] = lrow[mt][1] = 0.f;
        #pragma unroll
        for (int j = 0; j < 8; j++)
            o[mt][j][0] = o[mt][j][1] = o[mt][j][2] = o[mt][j][3] = 0.f;
    }

    for (int t = 0; t < NSEQ/64; t++) {
        if (t + 1 < NSEQ/64) {
            const __half* Kt = Kg + (size_t)(t+1) * 64 * DH;
            unsigned kdst = sbase + (unsigned)((128 + ((t+1)&1)*128)*LDH*2);
            unsigned vdst = kdst + (unsigned)(64*LDH*2);
            #pragma unroll
            for (int it = 0; it < 4; it++) {
                int i = tid + 128*it, r = i >> 3, c8 = (i & 7)*8;
                cp16(kdst + (unsigned)((r*LDH + c8)*2), &Kt[r*DH + c8]);
                cp16(vdst + (unsigned)((r*LDH + c8)*2), &VTg[(size_t)r*NSEQ + (t+1)*64 + c8]);
            }
            cp_commit();
            cp_wait<1>();
        } else {
            cp_wait<0>();
        }
        __syncthreads();

        const unsigned kB = sbase + (unsigned)((128 + (t&1)*128)*LDH*2) + bOff;
        const unsigned vB = kB + (unsigned)(64*LDH*2);

        // ---- S = Q K^T  (Q from registers; per warp 2 m-tiles x 8 n-tiles) ----
        float s[2][8][4];
        #pragma unroll
        for (int mt = 0; mt < 2; mt++)
            #pragma unroll
            for (int j = 0; j < 8; j++)
                s[mt][j][0] = s[mt][j][1] = s[mt][j][2] = s[mt][j][3] = 0.f;

        #pragma unroll
        for (int ks = 0; ks < 4; ks++) {
            const int kk = ks * 16;
            unsigned bf[8][2];
            #pragma unroll
            for (int j = 0; j < 8; j++)
                ldsm2(bf[j][0], bf[j][1], kB + (unsigned)((j*8*LDH + kk) * 2));
            #pragma unroll
            for (int mt = 0; mt < 2; mt++)
                #pragma unroll
                for (int j = 0; j < 8; j++) mma16(s[mt][j], qf[mt][ks], bf[j]);
        }

        // ---- online softmax (log2 domain), P packed into registers ----
        unsigned pp[2][8][2];
        bool resc = false;
        float al[2], ah[2];
        #pragma unroll
        for (int mt = 0; mt < 2; mt++) {
            float mxl = -1e30f, mxh = -1e30f;
            #pragma unroll
            for (int j = 0; j < 8; j++) {
                mxl = fmaxf(mxl, fmaxf(s[mt][j][0], s[mt][j][1]));
                mxh = fmaxf(mxh, fmaxf(s[mt][j][2], s[mt][j][3]));
            }
            mxl = fmaxf(mxl, __shfl_xor_sync(0xffffffffu, mxl, 1));
            mxl = fmaxf(mxl, __shfl_xor_sync(0xffffffffu, mxl, 2));
            mxh = fmaxf(mxh, __shfl_xor_sync(0xffffffffu, mxh, 1));
            mxh = fmaxf(mxh, __shfl_xor_sync(0xffffffffu, mxh, 2));
            float mln = fmaxf(mrow[mt][0], mxl);
            float mhn = fmaxf(mrow[mt][1], mxh);
            al[mt] = exp2f(mrow[mt][0] - mln);
            ah[mt] = exp2f(mrow[mt][1] - mhn);
            resc |= (mln > mrow[mt][0]) | (mhn > mrow[mt][1]);
            mrow[mt][0] = mln; mrow[mt][1] = mhn;
            float sl = 0.f, sh = 0.f;
            #pragma unroll
            for (int j = 0; j < 8; j++) {
                __half2 hl = __floats2half2_rn(exp2f(s[mt][j][0] - mln),
                                               exp2f(s[mt][j][1] - mln));
                __half2 hh = __floats2half2_rn(exp2f(s[mt][j][2] - mhn),
                                               exp2f(s[mt][j][3] - mhn));
                float2 fl = __half22float2(hl), fh = __half22float2(hh);
                sl += fl.x + fl.y; sh += fh.x + fh.y;
                pp[mt][j][0] = *(unsigned*)&hl;
                pp[mt][j][1] = *(unsigned*)&hh;
            }
            lrow[mt][0] = lrow[mt][0]*al[mt] + sl;   // al/ah == 1 when no rescale
            lrow[mt][1] = lrow[mt][1]*ah[mt] + sh;
        }
        if (__any_sync(0xffffffffu, resc)) {
            #pragma unroll
            for (int mt = 0; mt < 2; mt++)
                #pragma unroll
                for (int j = 0; j < 8; j++) {
                    o[mt][j][0] *= al[mt]; o[mt][j][1] *= al[mt];
                    o[mt][j][2] *= ah[mt]; o[mt][j][3] *= ah[mt];
                }
        }

        // ---- O += P V ----
        #pragma unroll
        for (int ks = 0; ks < 4; ks++) {
            const int kc = ks * 16;
            unsigned bf[8][2];
            #pragma unroll
            for (int jd = 0; jd < 8; jd++)
                ldsm2(bf[jd][0], bf[jd][1], vB + (unsigned)((jd*8*LDH + kc) * 2));
            #pragma unroll
            for (int mt = 0; mt < 2; mt++) {
                unsigned af[4] = { pp[mt][2*ks][0], pp[mt][2*ks][1],
                                   pp[mt][2*ks+1][0], pp[mt][2*ks+1][1] };
                #pragma unroll
                for (int jd = 0; jd < 8; jd++) mma16(o[mt][jd], af, bf[jd]);
            }
        }
        __syncthreads();
    }

    // ---- epilogue: quad-reduce partial sums, fp16 out to g_attnh ----
    #pragma unroll
    for (int mt = 0; mt < 2; mt++) {
        lrow[mt][0] += __shfl_xor_sync(0xffffffffu, lrow[mt][0], 1);
        lrow[mt][0] += __shfl_xor_sync(0xffffffffu, lrow[mt][0], 2);
        lrow[mt][1] += __shfl_xor_sync(0xffffffffu, lrow[mt][1], 1);
        lrow[mt][1] += __shfl_xor_sync(0xffffffffu, lrow[mt][1], 2);
        float il = 1.0f / lrow[mt][0], ih = 1.0f / lrow[mt][1];
        int rowl = q0 + w*32 + mt*16 + (lane >> 2);
        size_t basel = ((size_t)(b*NSEQ + rowl))*CDIM + h*DH + (lane & 3)*2;
        size_t baseh = basel + (size_t)8*CDIM;
        #pragma unroll
        for (int j = 0; j < 8; j++) {
            *(unsigned*)&g_attnh[basel + j*8] = pack2(o[mt][j][0]*il, o[mt][j][1]*il);
            *(unsigned*)&g_attnh[baseh + j*8] = pack2(o[mt][j][2]*ih, o[mt][j][3]*ih);
        }
    }
}

// ---------------------------------------------------------------------------
extern "C" void kernel_launch(void* const* d_in, const int* in_sizes, int n_in,
                              void* d_out, int out_size)
{
    const float* x        = (const float*)d_in[0];
    const float* w_qkv_a  = (const float*)d_in[1];
    const float* w_qkv_b  = (const float*)d_in[2];
    const float* w_proj_a = (const float*)d_in[3];
    const float* b_proj_a = (const float*)d_in[4];
    const float* w_proj_b = (const float*)d_in[5];
    const float* b_proj_b = (const float*)d_in[6];
    float* out = (float*)d_out;

    __half *pwah = nullptr, *phh = nullptr, *ph2h = nullptr, *pattnh = nullptr;
    cudaGetSymbolAddress((void**)&pwah,   g_wah);
    cudaGetSymbolAddress((void**)&phh,    g_hh);
    cudaGetSymbolAddress((void**)&ph2h,   g_h2h);
    cudaGetSymbolAddress((void**)&pattnh, g_attnh);

    static bool attr_set = false;
    if (!attr_set) {
        cudaFuncSetAttribute(flash_mma_kernel,
                             cudaFuncAttributeMaxDynamicSharedMemorySize, FLASH_SMEM);
        attr_set = true;
    }

    // 0. fp16 weight staging for the two K=1024 "A" GEMMs
    convert_w_kernel<<<64, 256>>>(w_qkv_a, w_proj_a);
    // 1. h = gelu(x @ w_qkv_a)                 fp16 [4096,64]
    lowrank_a_mma_kernel<false><<<MTOT/32, 64>>>(x, nullptr, pwah, nullptr, phh);
    // 2. qkv = h @ w_qkv_b (mma) -> q (x0.125*log2e), k, vT  (fp16)
    expand_mma_kernel<<<dim3(3*CDIM/128, MTOT/64), 128>>>(w_qkv_b);
    // 3. fp16 tensor-core flash attention -> g_attnh [B,N,C] fp16
    flash_mma_kernel<<<dim3(NSEQ/128, BD*HEADS), 128, FLASH_SMEM>>>();
    // 4. h2 = gelu(attn @ w_proj_a + b_proj_a) fp16 [4096,64]
    lowrank_a_mma_kernel<true><<<MTOT/32, 64>>>(nullptr, pattnh, pwah + KDIM*RANK,
                                                b_proj_a, ph2h);
    // 5. y = h2 @ w_proj_b + b_proj_b (mma)    fp32 [4096,1024]
    lowrank_out_mma_kernel<<<dim3(CDIM/128, MTOT/64), 128>>>(w_proj_b, b_proj_b, out);
}

// round 13
// speedup vs baseline: 1.0709x; 1.0049x over previous
#include <cuda_runtime.h>
#include <cuda_fp16.h>
#include <math.h>

#define BD    2
#define NSEQ  2048
#define CDIM  1024
#define RANK  64
#define HEADS 16
#define DH    64
#define MTOT  (BD*NSEQ)   // 4096
#define KDIM  1024

// Scratch (device globals: no allocation allowed in kernel_launch)
__device__ __half g_wah [2*KDIM*RANK];          // fp16 w_qkv_a | w_proj_a
__device__ __half g_hh  [MTOT*RANK];            // gelu(x @ w_qkv_a), fp16
__device__ __half g_h2h [MTOT*RANK];            // gelu(attn @ w_proj_a + b), fp16
__device__ __half g_qh  [BD*HEADS*NSEQ*DH];     // Q * 0.125*log2e, fp16 [bh][n][d]
__device__ __half g_kh  [BD*HEADS*NSEQ*DH];     // K fp16               [bh][n][d]
__device__ __half g_vTh [BD*HEADS*DH*NSEQ];     // V^T fp16             [bh][d][n]
__device__ __half g_attnh[MTOT*CDIM];           // attention out [B,N,C] fp16

__device__ __forceinline__ float gelu_exact(float v) {
    return 0.5f * v * (1.0f + erff(v * 0.70710678118654752440f));
}
__device__ __forceinline__ unsigned pack2(float a, float b) {
    __half2 h = __floats2half2_rn(a, b);
    return *(unsigned*)&h;
}
__device__ __forceinline__ void ldsm4(unsigned &r0, unsigned &r1, unsigned &r2, unsigned &r3, unsigned a) {
    asm volatile("ldmatrix.sync.aligned.m8n8.x4.shared.b16 {%0,%1,%2,%3}, [%4];"
                 : "=r"(r0),"=r"(r1),"=r"(r2),"=r"(r3) : "r"(a));
}
__device__ __forceinline__ void ldsm2(unsigned &r0, unsigned &r1, unsigned a) {
    asm volatile("ldmatrix.sync.aligned.m8n8.x2.shared.b16 {%0,%1}, [%2];"
                 : "=r"(r0),"=r"(r1) : "r"(a));
}
__device__ __forceinline__ void ldsm2t(unsigned &r0, unsigned &r1, unsigned a) {
    asm volatile("ldmatrix.sync.aligned.m8n8.x2.trans.shared.b16 {%0,%1}, [%2];"
                 : "=r"(r0),"=r"(r1) : "r"(a));
}
__device__ __forceinline__ void mma16(float* c, const unsigned* a, const unsigned* b) {
    asm volatile("mma.sync.aligned.m16n8k16.row.col.f32.f16.f16.f32 "
                 "{%0,%1,%2,%3},{%4,%5,%6,%7},{%8,%9},{%0,%1,%2,%3};"
                 : "+f"(c[0]),"+f"(c[1]),"+f"(c[2]),"+f"(c[3])
                 : "r"(a[0]),"r"(a[1]),"r"(a[2]),"r"(a[3]),"r"(b[0]),"r"(b[1]));
}
__device__ __forceinline__ void cp16(unsigned dst, const void* src) {
    asm volatile("cp.async.cg.shared.global [%0], [%1], 16;" :: "r"(dst), "l"(src));
}
__device__ __forceinline__ void cp_commit() { asm volatile("cp.async.commit_group;"); }
template<int N> __device__ __forceinline__ void cp_wait() {
    asm volatile("cp.async.wait_group %0;" :: "n"(N));
}

// ---------------------------------------------------------------------------
// One-shot weight converter: w_qkv_a, w_proj_a (fp32 [1024][64]) -> g_wah fp16.
// ---------------------------------------------------------------------------
__global__ __launch_bounds__(256) void convert_w_kernel(
    const float* __restrict__ wa, const float* __restrict__ wpa)
{
    int idx = blockIdx.x * 256 + threadIdx.x;
    float4 a = *(const float4*)&wa[idx * 4];
    float4 b = *(const float4*)&wpa[idx * 4];
    uint2 ua; ua.x = pack2(a.x, a.y); ua.y = pack2(a.z, a.w);
    uint2 ub; ub.x = pack2(b.x, b.y); ub.y = pack2(b.z, b.w);
    *(uint2*)&g_wah[idx * 4]               = ua;
    *(uint2*)&g_wah[KDIM*RANK + idx * 4]   = ub;
}

// ---------------------------------------------------------------------------
// out_fp16[M,64] = gelu(X[M,1024] @ W[1024,64] (+ bias)) via fp16 mma.
// X fp32 (XH=false) or fp16 (XH=true). 32-row tile, 64 threads (2 warps).
// ---------------------------------------------------------------------------
template<bool XH>
__global__ __launch_bounds__(64) void lowrank_a_mma_kernel(
    const float* __restrict__ Xf, const __half* __restrict__ Xh,
    const __half* __restrict__ Wh, const float* __restrict__ bias,
    __half* __restrict__ out)
{
    __shared__ __align__(16) __half Xs[32*72];
    __shared__ __align__(16) __half Ws[64*72];
    const int tid = threadIdx.x, lane = tid & 31, w = tid >> 5;
    const int m0 = blockIdx.x * 32;

    float4 xreg[8];
    uint4  xreg16[4];
    uint4  wreg[8];

    if (XH) {
        #pragma unroll
        for (int ii = 0; ii < 4; ii++) {
            int idx = tid + 64*ii, r = idx >> 3, c8 = (idx & 7) * 8;
            xreg16[ii] = *(const uint4*)&Xh[(m0 + r)*KDIM + c8];
        }
    } else {
        #pragma unroll
        for (int ii = 0; ii < 8; ii++) {
            int idx = tid + 64*ii, r = idx >> 4, c4 = (idx & 15) * 4;
            xreg[ii] = *(const float4*)&Xf[(m0 + r)*KDIM + c4];
        }
    }
    #pragma unroll
    for (int ii = 0; ii < 8; ii++) {
        int idx = tid + 64*ii, r = idx >> 3, c8 = (idx & 7) * 8;
        wreg[ii] = *(const uint4*)&Wh[r*RANK + c8];
    }

    const unsigned hA = (unsigned)__cvta_generic_to_shared(Xs)
                      + (unsigned)(((w*16 + (lane & 15))*72 + (lane >> 4)*8) * 2);
    const unsigned wB = (unsigned)__cvta_generic_to_shared(Ws)
                      + (unsigned)(((lane & 15)*72) * 2);

    float acc[8][4] = {};
    #pragma unroll 1
    for (int ch = 0; ch < KDIM/64; ch++) {
        if (XH) {
            #pragma unroll
            for (int ii = 0; ii < 4; ii++) {
                int idx = tid + 64*ii, r = idx >> 3, c8 = (idx & 7) * 8;
                *(uint4*)&Xs[r*72 + c8] = xreg16[ii];
            }
        } else {
            #pragma unroll
            for (int ii = 0; ii < 8; ii++) {
                int idx = tid + 64*ii, r = idx >> 4, c4 = (idx & 15) * 4;
                uint2 u; u.x = pack2(xreg[ii].x, xreg[ii].y);
                u.y = pack2(xreg[ii].z, xreg[ii].w);
                *(uint2*)&Xs[r*72 + c4] = u;
            }
        }
        #pragma unroll
        for (int ii = 0; ii < 8; ii++) {
            int idx = tid + 64*ii, r = idx >> 3, c8 = (idx & 7) * 8;
            *(uint4*)&Ws[r*72 + c8] = wreg[ii];
        }
        __syncthreads();
        if (ch + 1 < KDIM/64) {
            const int k0 = (ch + 1) * 64;
            if (XH) {
                #pragma unroll
                for (int ii = 0; ii < 4; ii++) {
                    int idx = tid + 64*ii, r = idx >> 3, c8 = (idx & 7) * 8;
                    xreg16[ii] = *(const uint4*)&Xh[(m0 + r)*KDIM + k0 + c8];
                }
            } else {
                #pragma unroll
                for (int ii = 0; ii < 8; ii++) {
                    int idx = tid + 64*ii, r = idx >> 4, c4 = (idx & 15) * 4;
                    xreg[ii] = *(const float4*)&Xf[(m0 + r)*KDIM + k0 + c4];
                }
            }
            #pragma unroll
            for (int ii = 0; ii < 8; ii++) {
                int idx = tid + 64*ii, r = idx >> 3, c8 = (idx & 7) * 8;
                wreg[ii] = *(const uint4*)&Wh[(k0 + r)*RANK + c8];
            }
        }
        #pragma unroll
        for (int ks = 0; ks < 4; ks++) {
            const int kk = ks * 16;
            unsigned af[4];
            ldsm4(af[0], af[1], af[2], af[3], hA + (unsigned)(kk * 2));
            #pragma unroll
            for (int j = 0; j < 8; j++) {
                unsigned bf[2];
                ldsm2t(bf[0], bf[1], wB + (unsigned)((kk*72 + j*8) * 2));
                mma16(acc[j], af, bf);
            }
        }
        __syncthreads();
    }

    const int rA = w*16 + (lane >> 2);
    #pragma unroll
    for (int j = 0; j < 8; j++) {
        int n = j*8 + (lane & 3)*2;
        float b0 = 0.f, b1 = 0.f;
        if (bias) { float2 bv = *(const float2*)&bias[n]; b0 = bv.x; b1 = bv.y; }
        *(unsigned*)&out[(m0 + rA    )*RANK + n] =
            pack2(gelu_exact(acc[j][0] + b0), gelu_exact(acc[j][1] + b1));
        *(unsigned*)&out[(m0 + rA + 8)*RANK + n] =
            pack2(gelu_exact(acc[j][2] + b0), gelu_exact(acc[j][3] + b1));
    }
}

// ---------------------------------------------------------------------------
// qkv = g_hh[4096,64] @ w_qkv_b[64,3072] via fp16 mma ->
//   g_qh (x 0.125*log2e), g_kh, g_vTh (transposed via SMEM staging).
// ---------------------------------------------------------------------------
__global__ __launch_bounds__(128) void expand_mma_kernel(const float* __restrict__ Wb)
{
    __shared__ __align__(16) __half Hs[64*72];
    __shared__ __align__(16) __half Wsm[64*136];
    const int tid = threadIdx.x, lane = tid & 31, w = tid >> 5;
    const int n0 = blockIdx.x * 128;
    const int m0 = blockIdx.y * 64;

    #pragma unroll
    for (int ii = 0; ii < 4; ii++) {
        int idx = tid + 128*ii, r = idx >> 3, c8 = (idx & 7) * 8;
        *(uint4*)&Hs[r*72 + c8] = *(const uint4*)&g_hh[(m0 + r)*64 + c8];
    }
    #pragma unroll
    for (int ii = 0; ii < 16; ii++) {
        int idx = tid + 128*ii, r = idx >> 5, c4 = (idx & 31) * 4;
        float4 v = *(const float4*)&Wb[r*(3*CDIM) + n0 + c4];
        uint2 u; u.x = pack2(v.x, v.y); u.y = pack2(v.z, v.w);
        *(uint2*)&Wsm[r*136 + c4] = u;
    }
    __syncthreads();

    const unsigned hA = (unsigned)__cvta_generic_to_shared(Hs)
                      + (unsigned)(((w*16 + (lane & 15))*72 + (lane >> 4)*8) * 2);
    const unsigned wB = (unsigned)__cvta_generic_to_shared(Wsm)
                      + (unsigned)(((lane & 15)*136) * 2);

    float acc[16][4] = {};
    #pragma unroll
    for (int ks = 0; ks < 4; ks++) {
        const int kk = ks * 16;
        unsigned af[4];
        ldsm4(af[0], af[1], af[2], af[3], hA + (unsigned)(kk * 2));
        #pragma unroll
        for (int j = 0; j < 16; j++) {
            unsigned bf[2];
            ldsm2t(bf[0], bf[1], wB + (unsigned)((kk*136 + j*8) * 2));
            mma16(acc[j], af, bf);
        }
    }

    const int comp = n0 >> 10;
    const int bb   = m0 >> 11;
    const int ns0  = m0 & 2047;
    const int rA   = w*16 + (lane >> 2);

    if (comp < 2) {
        const float sc = (comp == 0) ? (0.125f * 1.44269504088896341f) : 1.0f;
        __half* dst = (comp == 0) ? g_qh : g_kh;
        #pragma unroll
        for (int j = 0; j < 16; j++) {
            int gn   = (n0 + j*8 + (lane & 3)*2) & 1023;
            int head = gn >> 6, d = gn & 63;
            size_t base = ((size_t)(bb*HEADS + head)*NSEQ + ns0);
            *(unsigned*)&dst[(base + rA    )*DH + d] = pack2(acc[j][0]*sc, acc[j][1]*sc);
            *(unsigned*)&dst[(base + rA + 8)*DH + d] = pack2(acc[j][2]*sc, acc[j][3]*sc);
        }
    } else {
        __syncthreads();
        __half* Ts = Hs;
        #pragma unroll
        for (int j = 0; j < 16; j++) {
            int c = j*8 + (lane & 3)*2;
            Ts[(c+0)*72 + rA    ] = __float2half(acc[j][0]);
            Ts[(c+1)*72 + rA    ] = __float2half(acc[j][1]);
            Ts[(c+0)*72 + rA + 8] = __float2half(acc[j][2]);
            Ts[(c+1)*72 + rA + 8] = __float2half(acc[j][3]);
        }
        __syncthreads();
        int c    = tid;
        int gn   = (n0 + c) & 1023;
        int head = gn >> 6, d = gn & 63;
        size_t base = ((size_t)(bb*HEADS + head)*DH + d)*NSEQ + ns0;
        #pragma unroll
        for (int g = 0; g < 8; g++)
            *(uint4*)&g_vTh[base + g*8] = *(uint4*)&Ts[c*72 + g*8];
    }
}

// ---------------------------------------------------------------------------
// y[4096,1024] = g_h2h[4096,64] @ w_proj_b[64,1024] + b_proj_b   (fp16 mma)
// ---------------------------------------------------------------------------
__global__ __launch_bounds__(128) void lowrank_out_mma_kernel(
    const float* __restrict__ Wb, const float* __restrict__ bias,
    float* __restrict__ out)
{
    __shared__ __align__(16) __half Hs[64*72];
    __shared__ __align__(16) __half Wsm[64*136];
    const int tid = threadIdx.x, lane = tid & 31, w = tid >> 5;
    const int n0 = blockIdx.x * 128;
    const int m0 = blockIdx.y * 64;

    #pragma unroll
    for (int ii = 0; ii < 4; ii++) {
        int idx = tid + 128*ii, r = idx >> 3, c8 = (idx & 7) * 8;
        *(uint4*)&Hs[r*72 + c8] = *(const uint4*)&g_h2h[(m0 + r)*64 + c8];
    }
    #pragma unroll
    for (int ii = 0; ii < 16; ii++) {
        int idx = tid + 128*ii, r = idx >> 5, c4 = (idx & 31) * 4;
        float4 v = *(const float4*)&Wb[r*CDIM + n0 + c4];
        uint2 u; u.x = pack2(v.x, v.y); u.y = pack2(v.z, v.w);
        *(uint2*)&Wsm[r*136 + c4] = u;
    }
    __syncthreads();

    const unsigned hA = (unsigned)__cvta_generic_to_shared(Hs)
                      + (unsigned)(((w*16 + (lane & 15))*72 + (lane >> 4)*8) * 2);
    const unsigned wB = (unsigned)__cvta_generic_to_shared(Wsm)
                      + (unsigned)(((lane & 15)*136) * 2);

    float acc[16][4] = {};
    #pragma unroll
    for (int ks = 0; ks < 4; ks++) {
        const int kk = ks * 16;
        unsigned af[4];
        ldsm4(af[0], af[1], af[2], af[3], hA + (unsigned)(kk * 2));
        #pragma unroll
        for (int j = 0; j < 16; j++) {
            unsigned bf[2];
            ldsm2t(bf[0], bf[1], wB + (unsigned)((kk*136 + j*8) * 2));
            mma16(acc[j], af, bf);
        }
    }

    const int rA = w*16 + (lane >> 2);
    #pragma unroll
    for (int j = 0; j < 16; j++) {
        int n = n0 + j*8 + (lane & 3)*2;
        float2 bv = *(const float2*)&bias[n];
        size_t b0 = (size_t)(m0 + rA    )*CDIM + n;
        size_t b1 = (size_t)(m0 + rA + 8)*CDIM + n;
        *(float2*)&out[b0] = make_float2(acc[j][0] + bv.x, acc[j][1] + bv.y);
        *(float2*)&out[b1] = make_float2(acc[j][2] + bv.x, acc[j][3] + bv.y);
    }
}

// ---------------------------------------------------------------------------
// Flash attention, fp16 mma.m16n8k16, fp32 accum, exp2-domain softmax.
// Grid (NSEQ/128, B*H), 128 threads (4 warps), warp w owns q-rows [32w,32w+32).
// KV tile 64, 2-stage cp.async. Q fragments hoisted to registers.
// Per-m-tile softmax->PV interleave: softmax(mt1) is independent of PV(mt0),
// letting ptxas overlap MUFU/FMA work with the HMMA stream inside one warp.
// ---------------------------------------------------------------------------
#define LDH 72
#define FLASH_SMEM ((128 + 4*64) * LDH * 2)

__global__ __launch_bounds__(128) void flash_mma_kernel()
{
    extern __shared__ __align__(16) __half smh[];
    __half* Qs = smh;                                 // [128][LDH]

    const int tid  = threadIdx.x;
    const int lane = tid & 31, w = tid >> 5;
    const int bh = blockIdx.y;
    const int q0 = blockIdx.x * 128;
    const int b = bh >> 4, h = bh & 15;

    const __half* Qg  = g_qh  + ((size_t)bh * NSEQ + q0) * DH;
    const __half* Kg  = g_kh  + (size_t)bh * NSEQ * DH;
    const __half* VTg = g_vTh + (size_t)bh * DH * NSEQ;

    const unsigned sbase = (unsigned)__cvta_generic_to_shared(smh);

    // prologue: async-load KV tile 0 into buf 0
    {
        unsigned kdst = sbase + (unsigned)(128*LDH*2);
        unsigned vdst = kdst + (unsigned)(64*LDH*2);
        #pragma unroll
        for (int it = 0; it < 4; it++) {
            int i = tid + 128*it, r = i >> 3, c8 = (i & 7)*8;
            cp16(kdst + (unsigned)((r*LDH + c8)*2), &Kg[r*DH + c8]);
            cp16(vdst + (unsigned)((r*LDH + c8)*2), &VTg[(size_t)r*NSEQ + c8]);
        }
        cp_commit();
    }
    // Q tile to SMEM, then hoist fragments to registers
    #pragma unroll
    for (int it = 0; it < 8; it++) {
        int i = tid + 128 * it, r = i >> 3, c8 = (i & 7) * 8;
        *(uint4*)&Qs[r*LDH + c8] = *(const uint4*)&Qg[r*DH + c8];
    }
    __syncthreads();

    const unsigned aOff = (unsigned)((((lane & 15) * LDH) + (lane >> 4) * 8) * 2);
    const unsigned bOff = (unsigned)((((lane & 7) * LDH) + ((lane >> 3) & 1) * 8) * 2);

    unsigned qf[2][4][4];      // [m-tile][k-step][frag]
    #pragma unroll
    for (int mt = 0; mt < 2; mt++)
        #pragma unroll
        for (int ks = 0; ks < 4; ks++)
            ldsm4(qf[mt][ks][0], qf[mt][ks][1], qf[mt][ks][2], qf[mt][ks][3],
                  sbase + aOff + (unsigned)(((w*32 + mt*16)*LDH + ks*16) * 2));

    float o[2][8][4];
    float mrow[2][2], lrow[2][2];     // lrow = per-thread PARTIAL row sums
    #pragma unroll
    for (int mt = 0; mt < 2; mt++) {
        mrow[mt][0] = mrow[mt][1] = -1e30f;
        lrow[mt][0] = lrow[mt][1] = 0.f;
        #pragma unroll
        for (int j = 0; j < 8; j++)
            o[mt][j][0] = o[mt][j][1] = o[mt][j][2] = o[mt][j][3] = 0.f;
    }

    for (int t = 0; t < NSEQ/64; t++) {
        if (t + 1 < NSEQ/64) {
            const __half* Kt = Kg + (size_t)(t+1) * 64 * DH;
            unsigned kdst = sbase + (unsigned)((128 + ((t+1)&1)*128)*LDH*2);
            unsigned vdst = kdst + (unsigned)(64*LDH*2);
            #pragma unroll
            for (int it = 0; it < 4; it++) {
                int i = tid + 128*it, r = i >> 3, c8 = (i & 7)*8;
                cp16(kdst + (unsigned)((r*LDH + c8)*2), &Kt[r*DH + c8]);
                cp16(vdst + (unsigned)((r*LDH + c8)*2), &VTg[(size_t)r*NSEQ + (t+1)*64 + c8]);
            }
            cp_commit();
            cp_wait<1>();
        } else {
            cp_wait<0>();
        }
        __syncthreads();

        const unsigned kB = sbase + (unsigned)((128 + (t&1)*128)*LDH*2) + bOff;
        const unsigned vB = kB + (unsigned)(64*LDH*2);

        // ---- S = Q K^T  (Q from registers; per warp 2 m-tiles x 8 n-tiles) ----
        float s[2][8][4];
        #pragma unroll
        for (int mt = 0; mt < 2; mt++)
            #pragma unroll
            for (int j = 0; j < 8; j++)
                s[mt][j][0] = s[mt][j][1] = s[mt][j][2] = s[mt][j][3] = 0.f;

        #pragma unroll
        for (int ks = 0; ks < 4; ks++) {
            const int kk = ks * 16;
            unsigned bf[8][2];
            #pragma unroll
            for (int j = 0; j < 8; j++)
                ldsm2(bf[j][0], bf[j][1], kB + (unsigned)((j*8*LDH + kk) * 2));
            #pragma unroll
            for (int mt = 0; mt < 2; mt++)
                #pragma unroll
                for (int j = 0; j < 8; j++) mma16(s[mt][j], qf[mt][ks], bf[j]);
        }

        // ---- per m-tile: softmax then PV (softmax(mt1) overlaps PV(mt0)) ----
        #pragma unroll
        for (int mt = 0; mt < 2; mt++) {
            float mxl = -1e30f, mxh = -1e30f;
            #pragma unroll
            for (int j = 0; j < 8; j++) {
                mxl = fmaxf(mxl, fmaxf(s[mt][j][0], s[mt][j][1]));
                mxh = fmaxf(mxh, fmaxf(s[mt][j][2], s[mt][j][3]));
            }
            mxl = fmaxf(mxl, __shfl_xor_sync(0xffffffffu, mxl, 1));
            mxl = fmaxf(mxl, __shfl_xor_sync(0xffffffffu, mxl, 2));
            mxh = fmaxf(mxh, __shfl_xor_sync(0xffffffffu, mxh, 1));
            mxh = fmaxf(mxh, __shfl_xor_sync(0xffffffffu, mxh, 2));
            float mln = fmaxf(mrow[mt][0], mxl);
            float mhn = fmaxf(mrow[mt][1], mxh);
            float al = exp2f(mrow[mt][0] - mln);
            float ah = exp2f(mrow[mt][1] - mhn);
            bool resc = (mln > mrow[mt][0]) | (mhn > mrow[mt][1]);
            mrow[mt][0] = mln; mrow[mt][1] = mhn;

            unsigned pp[8][2];
            float sl = 0.f, sh = 0.f;
            #pragma unroll
            for (int j = 0; j < 8; j++) {
                __half2 hl = __floats2half2_rn(exp2f(s[mt][j][0] - mln),
                                               exp2f(s[mt][j][1] - mln));
                __half2 hh = __floats2half2_rn(exp2f(s[mt][j][2] - mhn),
                                               exp2f(s[mt][j][3] - mhn));
                float2 fl = __half22float2(hl), fh = __half22float2(hh);
                sl += fl.x + fl.y; sh += fh.x + fh.y;
                pp[j][0] = *(unsigned*)&hl;
                pp[j][1] = *(unsigned*)&hh;
            }
            lrow[mt][0] = lrow[mt][0]*al + sl;   // al/ah == 1 when no rescale
            lrow[mt][1] = lrow[mt][1]*ah + sh;
            if (__any_sync(0xffffffffu, resc)) {
                #pragma unroll
                for (int j = 0; j < 8; j++) {
                    o[mt][j][0] *= al; o[mt][j][1] *= al;
                    o[mt][j][2] *= ah; o[mt][j][3] *= ah;
                }
            }

            // O[mt] += P[mt] V
            #pragma unroll
            for (int ks = 0; ks < 4; ks++) {
                const int kc = ks * 16;
                unsigned af[4] = { pp[2*ks][0], pp[2*ks][1],
                                   pp[2*ks+1][0], pp[2*ks+1][1] };
                #pragma unroll
                for (int jd = 0; jd < 8; jd++) {
                    unsigned bf[2];
                    ldsm2(bf[0], bf[1], vB + (unsigned)((jd*8*LDH + kc) * 2));
                    mma16(o[mt][jd], af, bf);
                }
            }
        }
        __syncthreads();
    }

    // ---- epilogue: quad-reduce partial sums, fp16 out to g_attnh ----
    #pragma unroll
    for (int mt = 0; mt < 2; mt++) {
        lrow[mt][0] += __shfl_xor_sync(0xffffffffu, lrow[mt][0], 1);
        lrow[mt][0] += __shfl_xor_sync(0xffffffffu, lrow[mt][0], 2);
        lrow[mt][1] += __shfl_xor_sync(0xffffffffu, lrow[mt][1], 1);
        lrow[mt][1] += __shfl_xor_sync(0xffffffffu, lrow[mt][1], 2);
        float il = 1.0f / lrow[mt][0], ih = 1.0f / lrow[mt][1];
        int rowl = q0 + w*32 + mt*16 + (lane >> 2);
        size_t basel = ((size_t)(b*NSEQ + rowl))*CDIM + h*DH + (lane & 3)*2;
        size_t baseh = basel + (size_t)8*CDIM;
        #pragma unroll
        for (int j = 0; j < 8; j++) {
            *(unsigned*)&g_attnh[basel + j*8] = pack2(o[mt][j][0]*il, o[mt][j][1]*il);
            *(unsigned*)&g_attnh[baseh + j*8] = pack2(o[mt][j][2]*ih, o[mt][j][3]*ih);
        }
    }
}

// ---------------------------------------------------------------------------
extern "C" void kernel_launch(void* const* d_in, const int* in_sizes, int n_in,
                              void* d_out, int out_size)
{
    const float* x        = (const float*)d_in[0];
    const float* w_qkv_a  = (const float*)d_in[1];
    const float* w_qkv_b  = (const float*)d_in[2];
    const float* w_proj_a = (const float*)d_in[3];
    const float* b_proj_a = (const float*)d_in[4];
    const float* w_proj_b = (const float*)d_in[5];
    const float* b_proj_b = (const float*)d_in[6];
    float* out = (float*)d_out;

    __half *pwah = nullptr, *phh = nullptr, *ph2h = nullptr, *pattnh = nullptr;
    cudaGetSymbolAddress((void**)&pwah,   g_wah);
    cudaGetSymbolAddress((void**)&phh,    g_hh);
    cudaGetSymbolAddress((void**)&ph2h,   g_h2h);
    cudaGetSymbolAddress((void**)&pattnh, g_attnh);

    static bool attr_set = false;
    if (!attr_set) {
        cudaFuncSetAttribute(flash_mma_kernel,
                             cudaFuncAttributeMaxDynamicSharedMemorySize, FLASH_SMEM);
        attr_set = true;
    }

    // 0. fp16 weight staging for the two K=1024 "A" GEMMs
    convert_w_kernel<<<64, 256>>>(w_qkv_a, w_proj_a);
    // 1. h = gelu(x @ w_qkv_a)                 fp16 [4096,64]
    lowrank_a_mma_kernel<false><<<MTOT/32, 64>>>(x, nullptr, pwah, nullptr, phh);
    // 2. qkv = h @ w_qkv_b (mma) -> q (x0.125*log2e), k, vT  (fp16)
    expand_mma_kernel<<<dim3(3*CDIM/128, MTOT/64), 128>>>(w_qkv_b);
    // 3. fp16 tensor-core flash attention -> g_attnh [B,N,C] fp16
    flash_mma_kernel<<<dim3(NSEQ/128, BD*HEADS), 128, FLASH_SMEM>>>();
    // 4. h2 = gelu(attn @ w_proj_a + b_proj_a) fp16 [4096,64]
    lowrank_a_mma_kernel<true><<<MTOT/32, 64>>>(nullptr, pattnh, pwah + KDIM*RANK,
                                                b_proj_a, ph2h);
    // 5. y = h2 @ w_proj_b + b_proj_b (mma)    fp32 [4096,1024]
    lowrank_out_mma_kernel<<<dim3(CDIM/128, MTOT/64), 128>>>(w_proj_b, b_proj_b, out);
}

// round 15
// speedup vs baseline: 1.1128x; 1.0391x over previous
#include <cuda_runtime.h>
#include <cuda_fp16.h>
#include <math.h>

#define BD    2
#define NSEQ  2048
#define CDIM  1024
#define RANK  64
#define HEADS 16
#define DH    64
#define MTOT  (BD*NSEQ)   // 4096
#define KDIM  1024

// Scratch (device globals: no allocation allowed in kernel_launch)
__device__ __half g_wah [2*KDIM*RANK];          // fp16 w_qkv_a | w_proj_a
__device__ __half g_hh  [MTOT*RANK];            // gelu(x @ w_qkv_a), fp16
__device__ __half g_h2h [MTOT*RANK];            // gelu(attn @ w_proj_a + b), fp16
__device__ __half g_qh  [BD*HEADS*NSEQ*DH];     // Q * 0.125*log2e, fp16 [bh][n][d]
__device__ __half g_kh  [BD*HEADS*NSEQ*DH];     // K fp16               [bh][n][d]
__device__ __half g_vTh [BD*HEADS*DH*NSEQ];     // V^T fp16             [bh][d][n]
__device__ __half g_attnh[MTOT*CDIM];           // attention out [B,N,C] fp16

__device__ __forceinline__ float gelu_exact(float v) {
    return 0.5f * v * (1.0f + erff(v * 0.70710678118654752440f));
}
__device__ __forceinline__ unsigned pack2(float a, float b) {
    __half2 h = __floats2half2_rn(a, b);
    return *(unsigned*)&h;
}
__device__ __forceinline__ unsigned ex2_h2(unsigned d) {
    unsigned r;
    asm("ex2.approx.f16x2 %0, %1;" : "=r"(r) : "r"(d));
    return r;
}
__device__ __forceinline__ void ldsm4(unsigned &r0, unsigned &r1, unsigned &r2, unsigned &r3, unsigned a) {
    asm volatile("ldmatrix.sync.aligned.m8n8.x4.shared.b16 {%0,%1,%2,%3}, [%4];"
                 : "=r"(r0),"=r"(r1),"=r"(r2),"=r"(r3) : "r"(a));
}
__device__ __forceinline__ void ldsm2(unsigned &r0, unsigned &r1, unsigned a) {
    asm volatile("ldmatrix.sync.aligned.m8n8.x2.shared.b16 {%0,%1}, [%2];"
                 : "=r"(r0),"=r"(r1) : "r"(a));
}
__device__ __forceinline__ void ldsm2t(unsigned &r0, unsigned &r1, unsigned a) {
    asm volatile("ldmatrix.sync.aligned.m8n8.x2.trans.shared.b16 {%0,%1}, [%2];"
                 : "=r"(r0),"=r"(r1) : "r"(a));
}
__device__ __forceinline__ void mma16(float* c, const unsigned* a, const unsigned* b) {
    asm volatile("mma.sync.aligned.m16n8k16.row.col.f32.f16.f16.f32 "
                 "{%0,%1,%2,%3},{%4,%5,%6,%7},{%8,%9},{%0,%1,%2,%3};"
                 : "+f"(c[0]),"+f"(c[1]),"+f"(c[2]),"+f"(c[3])
                 : "r"(a[0]),"r"(a[1]),"r"(a[2]),"r"(a[3]),"r"(b[0]),"r"(b[1]));
}
__device__ __forceinline__ void cp16(unsigned dst, const void* src) {
    asm volatile("cp.async.cg.shared.global [%0], [%1], 16;" :: "r"(dst), "l"(src));
}
__device__ __forceinline__ void cp_commit() { asm volatile("cp.async.commit_group;"); }
template<int N> __device__ __forceinline__ void cp_wait() {
    asm volatile("cp.async.wait_group %0;" :: "n"(N));
}

// ---------------------------------------------------------------------------
// One-shot weight converter: w_qkv_a, w_proj_a (fp32 [1024][64]) -> g_wah fp16.
// ---------------------------------------------------------------------------
__global__ __launch_bounds__(256) void convert_w_kernel(
    const float* __restrict__ wa, const float* __restrict__ wpa)
{
    int idx = blockIdx.x * 256 + threadIdx.x;
    float4 a = *(const float4*)&wa[idx * 4];
    float4 b = *(const float4*)&wpa[idx * 4];
    uint2 ua; ua.x = pack2(a.x, a.y); ua.y = pack2(a.z, a.w);
    uint2 ub; ub.x = pack2(b.x, b.y); ub.y = pack2(b.z, b.w);
    *(uint2*)&g_wah[idx * 4]               = ua;
    *(uint2*)&g_wah[KDIM*RANK + idx * 4]   = ub;
}

// ---------------------------------------------------------------------------
// out_fp16[M,64] = gelu(X[M,1024] @ W[1024,64] (+ bias)) via fp16 mma.
// X fp32 (XH=false) or fp16 (XH=true). 32-row tile, 64 threads (2 warps).
// ---------------------------------------------------------------------------
template<bool XH>
__global__ __launch_bounds__(64) void lowrank_a_mma_kernel(
    const float* __restrict__ Xf, const __half* __restrict__ Xh,
    const __half* __restrict__ Wh, const float* __restrict__ bias,
    __half* __restrict__ out)
{
    __shared__ __align__(16) __half Xs[32*72];
    __shared__ __align__(16) __half Ws[64*72];
    const int tid = threadIdx.x, lane = tid & 31, w = tid >> 5;
    const int m0 = blockIdx.x * 32;

    float4 xreg[8];
    uint4  xreg16[4];
    uint4  wreg[8];

    if (XH) {
        #pragma unroll
        for (int ii = 0; ii < 4; ii++) {
            int idx = tid + 64*ii, r = idx >> 3, c8 = (idx & 7) * 8;
            xreg16[ii] = *(const uint4*)&Xh[(m0 + r)*KDIM + c8];
        }
    } else {
        #pragma unroll
        for (int ii = 0; ii < 8; ii++) {
            int idx = tid + 64*ii, r = idx >> 4, c4 = (idx & 15) * 4;
            xreg[ii] = *(const float4*)&Xf[(m0 + r)*KDIM + c4];
        }
    }
    #pragma unroll
    for (int ii = 0; ii < 8; ii++) {
        int idx = tid + 64*ii, r = idx >> 3, c8 = (idx & 7) * 8;
        wreg[ii] = *(const uint4*)&Wh[r*RANK + c8];
    }

    const unsigned hA = (unsigned)__cvta_generic_to_shared(Xs)
                      + (unsigned)(((w*16 + (lane & 15))*72 + (lane >> 4)*8) * 2);
    const unsigned wB = (unsigned)__cvta_generic_to_shared(Ws)
                      + (unsigned)(((lane & 15)*72) * 2);

    float acc[8][4] = {};
    #pragma unroll 1
    for (int ch = 0; ch < KDIM/64; ch++) {
        if (XH) {
            #pragma unroll
            for (int ii = 0; ii < 4; ii++) {
                int idx = tid + 64*ii, r = idx >> 3, c8 = (idx & 7) * 8;
                *(uint4*)&Xs[r*72 + c8] = xreg16[ii];
            }
        } else {
            #pragma unroll
            for (int ii = 0; ii < 8; ii++) {
                int idx = tid + 64*ii, r = idx >> 4, c4 = (idx & 15) * 4;
                uint2 u; u.x = pack2(xreg[ii].x, xreg[ii].y);
                u.y = pack2(xreg[ii].z, xreg[ii].w);
                *(uint2*)&Xs[r*72 + c4] = u;
            }
        }
        #pragma unroll
        for (int ii = 0; ii < 8; ii++) {
            int idx = tid + 64*ii, r = idx >> 3, c8 = (idx & 7) * 8;
            *(uint4*)&Ws[r*72 + c8] = wreg[ii];
        }
        __syncthreads();
        if (ch + 1 < KDIM/64) {
            const int k0 = (ch + 1) * 64;
            if (XH) {
                #pragma unroll
                for (int ii = 0; ii < 4; ii++) {
                    int idx = tid + 64*ii, r = idx >> 3, c8 = (idx & 7) * 8;
                    xreg16[ii] = *(const uint4*)&Xh[(m0 + r)*KDIM + k0 + c8];
                }
            } else {
                #pragma unroll
                for (int ii = 0; ii < 8; ii++) {
                    int idx = tid + 64*ii, r = idx >> 4, c4 = (idx & 15) * 4;
                    xreg[ii] = *(const float4*)&Xf[(m0 + r)*KDIM + k0 + c4];
                }
            }
            #pragma unroll
            for (int ii = 0; ii < 8; ii++) {
                int idx = tid + 64*ii, r = idx >> 3, c8 = (idx & 7) * 8;
                wreg[ii] = *(const uint4*)&Wh[(k0 + r)*RANK + c8];
            }
        }
        #pragma unroll
        for (int ks = 0; ks < 4; ks++) {
            const int kk = ks * 16;
            unsigned af[4];
            ldsm4(af[0], af[1], af[2], af[3], hA + (unsigned)(kk * 2));
            #pragma unroll
            for (int j = 0; j < 8; j++) {
                unsigned bf[2];
                ldsm2t(bf[0], bf[1], wB + (unsigned)((kk*72 + j*8) * 2));
                mma16(acc[j], af, bf);
            }
        }
        __syncthreads();
    }

    const int rA = w*16 + (lane >> 2);
    #pragma unroll
    for (int j = 0; j < 8; j++) {
        int n = j*8 + (lane & 3)*2;
        float b0 = 0.f, b1 = 0.f;
        if (bias) { float2 bv = *(const float2*)&bias[n]; b0 = bv.x; b1 = bv.y; }
        *(unsigned*)&out[(m0 + rA    )*RANK + n] =
            pack2(gelu_exact(acc[j][0] + b0), gelu_exact(acc[j][1] + b1));
        *(unsigned*)&out[(m0 + rA + 8)*RANK + n] =
            pack2(gelu_exact(acc[j][2] + b0), gelu_exact(acc[j][3] + b1));
    }
}

// ---------------------------------------------------------------------------
// qkv = g_hh[4096,64] @ w_qkv_b[64,3072] via fp16 mma ->
//   g_qh (x 0.125*log2e), g_kh, g_vTh (transposed via SMEM staging).
// ---------------------------------------------------------------------------
__global__ __launch_bounds__(128) void expand_mma_kernel(const float* __restrict__ Wb)
{
    __shared__ __align__(16) __half Hs[64*72];
    __shared__ __align__(16) __half Wsm[64*136];
    const int tid = threadIdx.x, lane = tid & 31, w = tid >> 5;
    const int n0 = blockIdx.x * 128;
    const int m0 = blockIdx.y * 64;

    #pragma unroll
    for (int ii = 0; ii < 4; ii++) {
        int idx = tid + 128*ii, r = idx >> 3, c8 = (idx & 7) * 8;
        *(uint4*)&Hs[r*72 + c8] = *(const uint4*)&g_hh[(m0 + r)*64 + c8];
    }
    #pragma unroll
    for (int ii = 0; ii < 16; ii++) {
        int idx = tid + 128*ii, r = idx >> 5, c4 = (idx & 31) * 4;
        float4 v = *(const float4*)&Wb[r*(3*CDIM) + n0 + c4];
        uint2 u; u.x = pack2(v.x, v.y); u.y = pack2(v.z, v.w);
        *(uint2*)&Wsm[r*136 + c4] = u;
    }
    __syncthreads();

    const unsigned hA = (unsigned)__cvta_generic_to_shared(Hs)
                      + (unsigned)(((w*16 + (lane & 15))*72 + (lane >> 4)*8) * 2);
    const unsigned wB = (unsigned)__cvta_generic_to_shared(Wsm)
                      + (unsigned)(((lane & 15)*136) * 2);

    float acc[16][4] = {};
    #pragma unroll
    for (int ks = 0; ks < 4; ks++) {
        const int kk = ks * 16;
        unsigned af[4];
        ldsm4(af[0], af[1], af[2], af[3], hA + (unsigned)(kk * 2));
        #pragma unroll
        for (int j = 0; j < 16; j++) {
            unsigned bf[2];
            ldsm2t(bf[0], bf[1], wB + (unsigned)((kk*136 + j*8) * 2));
            mma16(acc[j], af, bf);
        }
    }

    const int comp = n0 >> 10;
    const int bb   = m0 >> 11;
    const int ns0  = m0 & 2047;
    const int rA   = w*16 + (lane >> 2);

    if (comp < 2) {
        const float sc = (comp == 0) ? (0.125f * 1.44269504088896341f) : 1.0f;
        __half* dst = (comp == 0) ? g_qh : g_kh;
        #pragma unroll
        for (int j = 0; j < 16; j++) {
            int gn   = (n0 + j*8 + (lane & 3)*2) & 1023;
            int head = gn >> 6, d = gn & 63;
            size_t base = ((size_t)(bb*HEADS + head)*NSEQ + ns0);
            *(unsigned*)&dst[(base + rA    )*DH + d] = pack2(acc[j][0]*sc, acc[j][1]*sc);
            *(unsigned*)&dst[(base + rA + 8)*DH + d] = pack2(acc[j][2]*sc, acc[j][3]*sc);
        }
    } else {
        __syncthreads();
        __half* Ts = Hs;
        #pragma unroll
        for (int j = 0; j < 16; j++) {
            int c = j*8 + (lane & 3)*2;
            Ts[(c+0)*72 + rA    ] = __float2half(acc[j][0]);
            Ts[(c+1)*72 + rA    ] = __float2half(acc[j][1]);
            Ts[(c+0)*72 + rA + 8] = __float2half(acc[j][2]);
            Ts[(c+1)*72 + rA + 8] = __float2half(acc[j][3]);
        }
        __syncthreads();
        int c    = tid;
        int gn   = (n0 + c) & 1023;
        int head = gn >> 6, d = gn & 63;
        size_t base = ((size_t)(bb*HEADS + head)*DH + d)*NSEQ + ns0;
        #pragma unroll
        for (int g = 0; g < 8; g++)
            *(uint4*)&g_vTh[base + g*8] = *(uint4*)&Ts[c*72 + g*8];
    }
}

// ---------------------------------------------------------------------------
// y[4096,1024] = g_h2h[4096,64] @ w_proj_b[64,1024] + b_proj_b   (fp16 mma)
// ---------------------------------------------------------------------------
__global__ __launch_bounds__(128) void lowrank_out_mma_kernel(
    const float* __restrict__ Wb, const float* __restrict__ bias,
    float* __restrict__ out)
{
    __shared__ __align__(16) __half Hs[64*72];
    __shared__ __align__(16) __half Wsm[64*136];
    const int tid = threadIdx.x, lane = tid & 31, w = tid >> 5;
    const int n0 = blockIdx.x * 128;
    const int m0 = blockIdx.y * 64;

    #pragma unroll
    for (int ii = 0; ii < 4; ii++) {
        int idx = tid + 128*ii, r = idx >> 3, c8 = (idx & 7) * 8;
        *(uint4*)&Hs[r*72 + c8] = *(const uint4*)&g_h2h[(m0 + r)*64 + c8];
    }
    #pragma unroll
    for (int ii = 0; ii < 16; ii++) {
        int idx = tid + 128*ii, r = idx >> 5, c4 = (idx & 31) * 4;
        float4 v = *(const float4*)&Wb[r*CDIM + n0 + c4];
        uint2 u; u.x = pack2(v.x, v.y); u.y = pack2(v.z, v.w);
        *(uint2*)&Wsm[r*136 + c4] = u;
    }
    __syncthreads();

    const unsigned hA = (unsigned)__cvta_generic_to_shared(Hs)
                      + (unsigned)(((w*16 + (lane & 15))*72 + (lane >> 4)*8) * 2);
    const unsigned wB = (unsigned)__cvta_generic_to_shared(Wsm)
                      + (unsigned)(((lane & 15)*136) * 2);

    float acc[16][4] = {};
    #pragma unroll
    for (int ks = 0; ks < 4; ks++) {
        const int kk = ks * 16;
        unsigned af[4];
        ldsm4(af[0], af[1], af[2], af[3], hA + (unsigned)(kk * 2));
        #pragma unroll
        for (int j = 0; j < 16; j++) {
            unsigned bf[2];
            ldsm2t(bf[0], bf[1], wB + (unsigned)((kk*136 + j*8) * 2));
            mma16(acc[j], af, bf);
        }
    }

    const int rA = w*16 + (lane >> 2);
    #pragma unroll
    for (int j = 0; j < 16; j++) {
        int n = n0 + j*8 + (lane & 3)*2;
        float2 bv = *(const float2*)&bias[n];
        size_t b0 = (size_t)(m0 + rA    )*CDIM + n;
        size_t b1 = (size_t)(m0 + rA + 8)*CDIM + n;
        *(float2*)&out[b0] = make_float2(acc[j][0] + bv.x, acc[j][1] + bv.y);
        *(float2*)&out[b1] = make_float2(acc[j][2] + bv.x, acc[j][3] + bv.y);
    }
}

// ---------------------------------------------------------------------------
// Flash attention, fp16 mma.m16n8k16, fp32 accum, exp2-domain softmax with
// ex2.approx.f16x2 (half the MUFU ops) and packed-half2 max shuffles.
// Grid (NSEQ/128, B*H), 128 threads (4 warps), warp w owns q-rows [32w,32w+32).
// KV tile 64, 2-stage cp.async. Q fragments hoisted to registers.
// P in registers. Deferred l-reduction + conditional O rescale.
// ---------------------------------------------------------------------------
#define LDH 72
#define FLASH_SMEM ((128 + 4*64) * LDH * 2)

__global__ __launch_bounds__(128) void flash_mma_kernel()
{
    extern __shared__ __align__(16) __half smh[];
    __half* Qs = smh;                                 // [128][LDH]

    const int tid  = threadIdx.x;
    const int lane = tid & 31, w = tid >> 5;
    const int bh = blockIdx.y;
    const int q0 = blockIdx.x * 128;
    const int b = bh >> 4, h = bh & 15;

    const __half* Qg  = g_qh  + ((size_t)bh * NSEQ + q0) * DH;
    const __half* Kg  = g_kh  + (size_t)bh * NSEQ * DH;
    const __half* VTg = g_vTh + (size_t)bh * DH * NSEQ;

    const unsigned sbase = (unsigned)__cvta_generic_to_shared(smh);

    // prologue: async-load KV tile 0 into buf 0
    {
        unsigned kdst = sbase + (unsigned)(128*LDH*2);
        unsigned vdst = kdst + (unsigned)(64*LDH*2);
        #pragma unroll
        for (int it = 0; it < 4; it++) {
            int i = tid + 128*it, r = i >> 3, c8 = (i & 7)*8;
            cp16(kdst + (unsigned)((r*LDH + c8)*2), &Kg[r*DH + c8]);
            cp16(vdst + (unsigned)((r*LDH + c8)*2), &VTg[(size_t)r*NSEQ + c8]);
        }
        cp_commit();
    }
    // Q tile to SMEM, then hoist fragments to registers
    #pragma unroll
    for (int it = 0; it < 8; it++) {
        int i = tid + 128 * it, r = i >> 3, c8 = (i & 7) * 8;
        *(uint4*)&Qs[r*LDH + c8] = *(const uint4*)&Qg[r*DH + c8];
    }
    __syncthreads();

    const unsigned aOff = (unsigned)((((lane & 15) * LDH) + (lane >> 4) * 8) * 2);
    const unsigned bOff = (unsigned)((((lane & 7) * LDH) + ((lane >> 3) & 1) * 8) * 2);

    unsigned qf[2][4][4];      // [m-tile][k-step][frag]
    #pragma unroll
    for (int mt = 0; mt < 2; mt++)
        #pragma unroll
        for (int ks = 0; ks < 4; ks++)
            ldsm4(qf[mt][ks][0], qf[mt][ks][1], qf[mt][ks][2], qf[mt][ks][3],
                  sbase + aOff + (unsigned)(((w*32 + mt*16)*LDH + ks*16) * 2));

    float o[2][8][4];
    float mrow[2][2], lrow[2][2];     // lrow = per-thread PARTIAL row sums
    #pragma unroll
    for (int mt = 0; mt < 2; mt++) {
        mrow[mt][0] = mrow[mt][1] = -1e30f;
        lrow[mt][0] = lrow[mt][1] = 0.f;
        #pragma unroll
        for (int j = 0; j < 8; j++)
            o[mt][j][0] = o[mt][j][1] = o[mt][j][2] = o[mt][j][3] = 0.f;
    }

    for (int t = 0; t < NSEQ/64; t++) {
        if (t + 1 < NSEQ/64) {
            const __half* Kt = Kg + (size_t)(t+1) * 64 * DH;
            unsigned kdst = sbase + (unsigned)((128 + ((t+1)&1)*128)*LDH*2);
            unsigned vdst = kdst + (unsigned)(64*LDH*2);
            #pragma unroll
            for (int it = 0; it < 4; it++) {
                int i = tid + 128*it, r = i >> 3, c8 = (i & 7)*8;
                cp16(kdst + (unsigned)((r*LDH + c8)*2), &Kt[r*DH + c8]);
                cp16(vdst + (unsigned)((r*LDH + c8)*2), &VTg[(size_t)r*NSEQ + (t+1)*64 + c8]);
            }
            cp_commit();
            cp_wait<1>();
        } else {
            cp_wait<0>();
        }
        __syncthreads();

        const unsigned kB = sbase + (unsigned)((128 + (t&1)*128)*LDH*2) + bOff;
        const unsigned vB = kB + (unsigned)(64*LDH*2);

        // ---- S = Q K^T  (Q from registers; per warp 2 m-tiles x 8 n-tiles) ----
        float s[2][8][4];
        #pragma unroll
        for (int mt = 0; mt < 2; mt++)
            #pragma unroll
            for (int j = 0; j < 8; j++)
                s[mt][j][0] = s[mt][j][1] = s[mt][j][2] = s[mt][j][3] = 0.f;

        #pragma unroll
        for (int ks = 0; ks < 4; ks++) {
            const int kk = ks * 16;
            unsigned bf[8][2];
            #pragma unroll
            for (int j = 0; j < 8; j++)
                ldsm2(bf[j][0], bf[j][1], kB + (unsigned)((j*8*LDH + kk) * 2));
            #pragma unroll
            for (int mt = 0; mt < 2; mt++)
                #pragma unroll
                for (int j = 0; j < 8; j++) mma16(s[mt][j], qf[mt][ks], bf[j]);
        }

        // ---- per m-tile: softmax (f16x2 ex2, packed max shfl) then PV ----
        #pragma unroll
        for (int mt = 0; mt < 2; mt++) {
            float mxl = -1e30f, mxh = -1e30f;
            #pragma unroll
            for (int j = 0; j < 8; j++) {
                mxl = fmaxf(mxl, fmaxf(s[mt][j][0], s[mt][j][1]));
                mxh = fmaxf(mxh, fmaxf(s[mt][j][2], s[mt][j][3]));
            }
            // packed half2 quad-max (fp16-rounded max is safe: only shifts d by <=ulp)
            __half2 m2 = __floats2half2_rn(mxl, mxh);
            unsigned mu = *(unsigned*)&m2;
            unsigned s1 = __shfl_xor_sync(0xffffffffu, mu, 1);
            m2 = __hmax2(m2, *(__half2*)&s1);
            mu = *(unsigned*)&m2;
            unsigned s2 = __shfl_xor_sync(0xffffffffu, mu, 2);
            m2 = __hmax2(m2, *(__half2*)&s2);
            float2 mf = __half22float2(m2);

            float mln = fmaxf(mrow[mt][0], mf.x);
            float mhn = fmaxf(mrow[mt][1], mf.y);
            float al = exp2f(mrow[mt][0] - mln);
            float ah = exp2f(mrow[mt][1] - mhn);
            bool resc = (mln > mrow[mt][0]) | (mhn > mrow[mt][1]);
            mrow[mt][0] = mln; mrow[mt][1] = mhn;

            unsigned pp[8][2];
            float sl = 0.f, sh = 0.f;
            #pragma unroll
            for (int j = 0; j < 8; j++) {
                unsigned hl = ex2_h2(pack2(s[mt][j][0] - mln, s[mt][j][1] - mln));
                unsigned hh = ex2_h2(pack2(s[mt][j][2] - mhn, s[mt][j][3] - mhn));
                float2 fl = __half22float2(*(__half2*)&hl);
                float2 fh = __half22float2(*(__half2*)&hh);
                sl += fl.x + fl.y; sh += fh.x + fh.y;
                pp[j][0] = hl;
                pp[j][1] = hh;
            }
            lrow[mt][0] = lrow[mt][0]*al + sl;   // al/ah == 1 when no rescale
            lrow[mt][1] = lrow[mt][1]*ah + sh;
            if (__any_sync(0xffffffffu, resc)) {
                #pragma unroll
                for (int j = 0; j < 8; j++) {
                    o[mt][j][0] *= al; o[mt][j][1] *= al;
                    o[mt][j][2] *= ah; o[mt][j][3] *= ah;
                }
            }

            // O[mt] += P[mt] V
            #pragma unroll
            for (int ks = 0; ks < 4; ks++) {
                const int kc = ks * 16;
                unsigned af[4] = { pp[2*ks][0], pp[2*ks][1],
                                   pp[2*ks+1][0], pp[2*ks+1][1] };
                #pragma unroll
                for (int jd = 0; jd < 8; jd++) {
                    unsigned bf[2];
                    ldsm2(bf[0], bf[1], vB + (unsigned)((jd*8*LDH + kc) * 2));
                    mma16(o[mt][jd], af, bf);
                }
            }
        }
        __syncthreads();
    }

    // ---- epilogue: quad-reduce partial sums, fp16 out to g_attnh ----
    #pragma unroll
    for (int mt = 0; mt < 2; mt++) {
        lrow[mt][0] += __shfl_xor_sync(0xffffffffu, lrow[mt][0], 1);
        lrow[mt][0] += __shfl_xor_sync(0xffffffffu, lrow[mt][0], 2);
        lrow[mt][1] += __shfl_xor_sync(0xffffffffu, lrow[mt][1], 1);
        lrow[mt][1] += __shfl_xor_sync(0xffffffffu, lrow[mt][1], 2);
        float il = 1.0f / lrow[mt][0], ih = 1.0f / lrow[mt][1];
        int rowl = q0 + w*32 + mt*16 + (lane >> 2);
        size_t basel = ((size_t)(b*NSEQ + rowl))*CDIM + h*DH + (lane & 3)*2;
        size_t baseh = basel + (size_t)8*CDIM;
        #pragma unroll
        for (int j = 0; j < 8; j++) {
            *(unsigned*)&g_attnh[basel + j*8] = pack2(o[mt][j][0]*il, o[mt][j][1]*il);
            *(unsigned*)&g_attnh[baseh + j*8] = pack2(o[mt][j][2]*ih, o[mt][j][3]*ih);
        }
    }
}

// ---------------------------------------------------------------------------
extern "C" void kernel_launch(void* const* d_in, const int* in_sizes, int n_in,
                              void* d_out, int out_size)
{
    const float* x        = (const float*)d_in[0];
    const float* w_qkv_a  = (const float*)d_in[1];
    const float* w_qkv_b  = (const float*)d_in[2];
    const float* w_proj_a = (const float*)d_in[3];
    const float* b_proj_a = (const float*)d_in[4];
    const float* w_proj_b = (const float*)d_in[5];
    const float* b_proj_b = (const float*)d_in[6];
    float* out = (float*)d_out;

    __half *pwah = nullptr, *phh = nullptr, *ph2h = nullptr, *pattnh = nullptr;
    cudaGetSymbolAddress((void**)&pwah,   g_wah);
    cudaGetSymbolAddress((void**)&phh,    g_hh);
    cudaGetSymbolAddress((void**)&ph2h,   g_h2h);
    cudaGetSymbolAddress((void**)&pattnh, g_attnh);

    static bool attr_set = false;
    if (!attr_set) {
        cudaFuncSetAttribute(flash_mma_kernel,
                             cudaFuncAttributeMaxDynamicSharedMemorySize, FLASH_SMEM);
        attr_set = true;
    }

    // 0. fp16 weight staging for the two K=1024 "A" GEMMs
    convert_w_kernel<<<64, 256>>>(w_qkv_a, w_proj_a);
    // 1. h = gelu(x @ w_qkv_a)                 fp16 [4096,64]
    lowrank_a_mma_kernel<false><<<MTOT/32, 64>>>(x, nullptr, pwah, nullptr, phh);
    // 2. qkv = h @ w_qkv_b (mma) -> q (x0.125*log2e), k, vT  (fp16)
    expand_mma_kernel<<<dim3(3*CDIM/128, MTOT/64), 128>>>(w_qkv_b);
    // 3. fp16 tensor-core flash attention -> g_attnh [B,N,C] fp16
    flash_mma_kernel<<<dim3(NSEQ/128, BD*HEADS), 128, FLASH_SMEM>>>();
    // 4. h2 = gelu(attn @ w_proj_a + b_proj_a) fp16 [4096,64]
    lowrank_a_mma_kernel<true><<<MTOT/32, 64>>>(nullptr, pattnh, pwah + KDIM*RANK,
                                                b_proj_a, ph2h);
    // 5. y = h2 @ w_proj_b + b_proj_b (mma)    fp32 [4096,1024]
    lowrank_out_mma_kernel<<<dim3(CDIM/128, MTOT/64), 128>>>(w_proj_b, b_proj_b, out);
}

// round 16
// speedup vs baseline: 1.1270x; 1.0128x over previous
#include <cuda_runtime.h>
#include <cuda_fp16.h>
#include <math.h>

#define BD    2
#define NSEQ  2048
#define CDIM  1024
#define RANK  64
#define HEADS 16
#define DH    64
#define MTOT  (BD*NSEQ)   // 4096
#define KDIM  1024

// Scratch (device globals: no allocation allowed in kernel_launch)
__device__ __half g_wah [2*KDIM*RANK];          // fp16 w_qkv_a | w_proj_a
__device__ __half g_hh  [MTOT*RANK];            // gelu(x @ w_qkv_a), fp16
__device__ __half g_h2h [MTOT*RANK];            // gelu(attn @ w_proj_a + b), fp16
__device__ __half g_qh  [BD*HEADS*NSEQ*DH];     // Q * 0.125*log2e, fp16 [bh][n][d]
__device__ __half g_kh  [BD*HEADS*NSEQ*DH];     // K fp16               [bh][n][d]
__device__ __half g_vTh [BD*HEADS*DH*NSEQ];     // V^T fp16             [bh][d][n]
__device__ __half g_attnh[MTOT*CDIM];           // attention out [B,N,C] fp16

__device__ __forceinline__ float gelu_exact(float v) {
    return 0.5f * v * (1.0f + erff(v * 0.70710678118654752440f));
}
__device__ __forceinline__ unsigned pack2(float a, float b) {
    __half2 h = __floats2half2_rn(a, b);
    return *(unsigned*)&h;
}
__device__ __forceinline__ unsigned ex2_h2(unsigned d) {
    unsigned r;
    asm("ex2.approx.f16x2 %0, %1;" : "=r"(r) : "r"(d));
    return r;
}
__device__ __forceinline__ void ldsm4(unsigned &r0, unsigned &r1, unsigned &r2, unsigned &r3, unsigned a) {
    asm volatile("ldmatrix.sync.aligned.m8n8.x4.shared.b16 {%0,%1,%2,%3}, [%4];"
                 : "=r"(r0),"=r"(r1),"=r"(r2),"=r"(r3) : "r"(a));
}
__device__ __forceinline__ void ldsm2(unsigned &r0, unsigned &r1, unsigned a) {
    asm volatile("ldmatrix.sync.aligned.m8n8.x2.shared.b16 {%0,%1}, [%2];"
                 : "=r"(r0),"=r"(r1) : "r"(a));
}
__device__ __forceinline__ void ldsm2t(unsigned &r0, unsigned &r1, unsigned a) {
    asm volatile("ldmatrix.sync.aligned.m8n8.x2.trans.shared.b16 {%0,%1}, [%2];"
                 : "=r"(r0),"=r"(r1) : "r"(a));
}
__device__ __forceinline__ void mma16(float* c, const unsigned* a, const unsigned* b) {
    asm volatile("mma.sync.aligned.m16n8k16.row.col.f32.f16.f16.f32 "
                 "{%0,%1,%2,%3},{%4,%5,%6,%7},{%8,%9},{%0,%1,%2,%3};"
                 : "+f"(c[0]),"+f"(c[1]),"+f"(c[2]),"+f"(c[3])
                 : "r"(a[0]),"r"(a[1]),"r"(a[2]),"r"(a[3]),"r"(b[0]),"r"(b[1]));
}
__device__ __forceinline__ void cp16(unsigned dst, const void* src) {
    asm volatile("cp.async.cg.shared.global [%0], [%1], 16;" :: "r"(dst), "l"(src));
}
__device__ __forceinline__ void cp_commit() { asm volatile("cp.async.commit_group;"); }
template<int N> __device__ __forceinline__ void cp_wait() {
    asm volatile("cp.async.wait_group %0;" :: "n"(N));
}

// ---------------------------------------------------------------------------
// One-shot weight converter: w_qkv_a, w_proj_a (fp32 [1024][64]) -> g_wah fp16.
// ---------------------------------------------------------------------------
__global__ __launch_bounds__(256) void convert_w_kernel(
    const float* __restrict__ wa, const float* __restrict__ wpa)
{
    int idx = blockIdx.x * 256 + threadIdx.x;
    float4 a = *(const float4*)&wa[idx * 4];
    float4 b = *(const float4*)&wpa[idx * 4];
    uint2 ua; ua.x = pack2(a.x, a.y); ua.y = pack2(a.z, a.w);
    uint2 ub; ub.x = pack2(b.x, b.y); ub.y = pack2(b.z, b.w);
    *(uint2*)&g_wah[idx * 4]               = ua;
    *(uint2*)&g_wah[KDIM*RANK + idx * 4]   = ub;
}

// ---------------------------------------------------------------------------
// out_fp16[M,64] = gelu(X[M,1024] @ W[1024,64] (+ bias)) via fp16 mma.
// X fp32 (XH=false) or fp16 (XH=true). 32-row tile, 64 threads (2 warps).
// ---------------------------------------------------------------------------
template<bool XH>
__global__ __launch_bounds__(64) void lowrank_a_mma_kernel(
    const float* __restrict__ Xf, const __half* __restrict__ Xh,
    const __half* __restrict__ Wh, const float* __restrict__ bias,
    __half* __restrict__ out)
{
    __shared__ __align__(16) __half Xs[32*72];
    __shared__ __align__(16) __half Ws[64*72];
    const int tid = threadIdx.x, lane = tid & 31, w = tid >> 5;
    const int m0 = blockIdx.x * 32;

    float4 xreg[8];
    uint4  xreg16[4];
    uint4  wreg[8];

    if (XH) {
        #pragma unroll
        for (int ii = 0; ii < 4; ii++) {
            int idx = tid + 64*ii, r = idx >> 3, c8 = (idx & 7) * 8;
            xreg16[ii] = *(const uint4*)&Xh[(m0 + r)*KDIM + c8];
        }
    } else {
        #pragma unroll
        for (int ii = 0; ii < 8; ii++) {
            int idx = tid + 64*ii, r = idx >> 4, c4 = (idx & 15) * 4;
            xreg[ii] = *(const float4*)&Xf[(m0 + r)*KDIM + c4];
        }
    }
    #pragma unroll
    for (int ii = 0; ii < 8; ii++) {
        int idx = tid + 64*ii, r = idx >> 3, c8 = (idx & 7) * 8;
        wreg[ii] = *(const uint4*)&Wh[r*RANK + c8];
    }

    const unsigned hA = (unsigned)__cvta_generic_to_shared(Xs)
                      + (unsigned)(((w*16 + (lane & 15))*72 + (lane >> 4)*8) * 2);
    const unsigned wB = (unsigned)__cvta_generic_to_shared(Ws)
                      + (unsigned)(((lane & 15)*72) * 2);

    float acc[8][4] = {};
    #pragma unroll 1
    for (int ch = 0; ch < KDIM/64; ch++) {
        if (XH) {
            #pragma unroll
            for (int ii = 0; ii < 4; ii++) {
                int idx = tid + 64*ii, r = idx >> 3, c8 = (idx & 7) * 8;
                *(uint4*)&Xs[r*72 + c8] = xreg16[ii];
            }
        } else {
            #pragma unroll
            for (int ii = 0; ii < 8; ii++) {
                int idx = tid + 64*ii, r = idx >> 4, c4 = (idx & 15) * 4;
                uint2 u; u.x = pack2(xreg[ii].x, xreg[ii].y);
                u.y = pack2(xreg[ii].z, xreg[ii].w);
                *(uint2*)&Xs[r*72 + c4] = u;
            }
        }
        #pragma unroll
        for (int ii = 0; ii < 8; ii++) {
            int idx = tid + 64*ii, r = idx >> 3, c8 = (idx & 7) * 8;
            *(uint4*)&Ws[r*72 + c8] = wreg[ii];
        }
        __syncthreads();
        if (ch + 1 < KDIM/64) {
            const int k0 = (ch + 1) * 64;
            if (XH) {
                #pragma unroll
                for (int ii = 0; ii < 4; ii++) {
                    int idx = tid + 64*ii, r = idx >> 3, c8 = (idx & 7) * 8;
                    xreg16[ii] = *(const uint4*)&Xh[(m0 + r)*KDIM + k0 + c8];
                }
            } else {
                #pragma unroll
                for (int ii = 0; ii < 8; ii++) {
                    int idx = tid + 64*ii, r = idx >> 4, c4 = (idx & 15) * 4;
                    xreg[ii] = *(const float4*)&Xf[(m0 + r)*KDIM + k0 + c4];
                }
            }
            #pragma unroll
            for (int ii = 0; ii < 8; ii++) {
                int idx = tid + 64*ii, r = idx >> 3, c8 = (idx & 7) * 8;
                wreg[ii] = *(const uint4*)&Wh[(k0 + r)*RANK + c8];
            }
        }
        #pragma unroll
        for (int ks = 0; ks < 4; ks++) {
            const int kk = ks * 16;
            unsigned af[4];
            ldsm4(af[0], af[1], af[2], af[3], hA + (unsigned)(kk * 2));
            #pragma unroll
            for (int j = 0; j < 8; j++) {
                unsigned bf[2];
                ldsm2t(bf[0], bf[1], wB + (unsigned)((kk*72 + j*8) * 2));
                mma16(acc[j], af, bf);
            }
        }
        __syncthreads();
    }

    const int rA = w*16 + (lane >> 2);
    #pragma unroll
    for (int j = 0; j < 8; j++) {
        int n = j*8 + (lane & 3)*2;
        float b0 = 0.f, b1 = 0.f;
        if (bias) { float2 bv = *(const float2*)&bias[n]; b0 = bv.x; b1 = bv.y; }
        *(unsigned*)&out[(m0 + rA    )*RANK + n] =
            pack2(gelu_exact(acc[j][0] + b0), gelu_exact(acc[j][1] + b1));
        *(unsigned*)&out[(m0 + rA + 8)*RANK + n] =
            pack2(gelu_exact(acc[j][2] + b0), gelu_exact(acc[j][3] + b1));
    }
}

// ---------------------------------------------------------------------------
// qkv = g_hh[4096,64] @ w_qkv_b[64,3072] via fp16 mma ->
//   g_qh (x 0.125*log2e), g_kh, g_vTh (transposed via SMEM staging).
// ---------------------------------------------------------------------------
__global__ __launch_bounds__(128) void expand_mma_kernel(const float* __restrict__ Wb)
{
    __shared__ __align__(16) __half Hs[64*72];
    __shared__ __align__(16) __half Wsm[64*136];
    const int tid = threadIdx.x, lane = tid & 31, w = tid >> 5;
    const int n0 = blockIdx.x * 128;
    const int m0 = blockIdx.y * 64;

    #pragma unroll
    for (int ii = 0; ii < 4; ii++) {
        int idx = tid + 128*ii, r = idx >> 3, c8 = (idx & 7) * 8;
        *(uint4*)&Hs[r*72 + c8] = *(const uint4*)&g_hh[(m0 + r)*64 + c8];
    }
    #pragma unroll
    for (int ii = 0; ii < 16; ii++) {
        int idx = tid + 128*ii, r = idx >> 5, c4 = (idx & 31) * 4;
        float4 v = *(const float4*)&Wb[r*(3*CDIM) + n0 + c4];
        uint2 u; u.x = pack2(v.x, v.y); u.y = pack2(v.z, v.w);
        *(uint2*)&Wsm[r*136 + c4] = u;
    }
    __syncthreads();

    const unsigned hA = (unsigned)__cvta_generic_to_shared(Hs)
                      + (unsigned)(((w*16 + (lane & 15))*72 + (lane >> 4)*8) * 2);
    const unsigned wB = (unsigned)__cvta_generic_to_shared(Wsm)
                      + (unsigned)(((lane & 15)*136) * 2);

    float acc[16][4] = {};
    #pragma unroll
    for (int ks = 0; ks < 4; ks++) {
        const int kk = ks * 16;
        unsigned af[4];
        ldsm4(af[0], af[1], af[2], af[3], hA + (unsigned)(kk * 2));
        #pragma unroll
        for (int j = 0; j < 16; j++) {
            unsigned bf[2];
            ldsm2t(bf[0], bf[1], wB + (unsigned)((kk*136 + j*8) * 2));
            mma16(acc[j], af, bf);
        }
    }

    const int comp = n0 >> 10;
    const int bb   = m0 >> 11;
    const int ns0  = m0 & 2047;
    const int rA   = w*16 + (lane >> 2);

    if (comp < 2) {
        const float sc = (comp == 0) ? (0.125f * 1.44269504088896341f) : 1.0f;
        __half* dst = (comp == 0) ? g_qh : g_kh;
        #pragma unroll
        for (int j = 0; j < 16; j++) {
            int gn   = (n0 + j*8 + (lane & 3)*2) & 1023;
            int head = gn >> 6, d = gn & 63;
            size_t base = ((size_t)(bb*HEADS + head)*NSEQ + ns0);
            *(unsigned*)&dst[(base + rA    )*DH + d] = pack2(acc[j][0]*sc, acc[j][1]*sc);
            *(unsigned*)&dst[(base + rA + 8)*DH + d] = pack2(acc[j][2]*sc, acc[j][3]*sc);
        }
    } else {
        __syncthreads();
        __half* Ts = Hs;
        #pragma unroll
        for (int j = 0; j < 16; j++) {
            int c = j*8 + (lane & 3)*2;
            Ts[(c+0)*72 + rA    ] = __float2half(acc[j][0]);
            Ts[(c+1)*72 + rA    ] = __float2half(acc[j][1]);
            Ts[(c+0)*72 + rA + 8] = __float2half(acc[j][2]);
            Ts[(c+1)*72 + rA + 8] = __float2half(acc[j][3]);
        }
        __syncthreads();
        int c    = tid;
        int gn   = (n0 + c) & 1023;
        int head = gn >> 6, d = gn & 63;
        size_t base = ((size_t)(bb*HEADS + head)*DH + d)*NSEQ + ns0;
        #pragma unroll
        for (int g = 0; g < 8; g++)
            *(uint4*)&g_vTh[base + g*8] = *(uint4*)&Ts[c*72 + g*8];
    }
}

// ---------------------------------------------------------------------------
// y[4096,1024] = g_h2h[4096,64] @ w_proj_b[64,1024] + b_proj_b   (fp16 mma)
// ---------------------------------------------------------------------------
__global__ __launch_bounds__(128) void lowrank_out_mma_kernel(
    const float* __restrict__ Wb, const float* __restrict__ bias,
    float* __restrict__ out)
{
    __shared__ __align__(16) __half Hs[64*72];
    __shared__ __align__(16) __half Wsm[64*136];
    const int tid = threadIdx.x, lane = tid & 31, w = tid >> 5;
    const int n0 = blockIdx.x * 128;
    const int m0 = blockIdx.y * 64;

    #pragma unroll
    for (int ii = 0; ii < 4; ii++) {
        int idx = tid + 128*ii, r = idx >> 3, c8 = (idx & 7) * 8;
        *(uint4*)&Hs[r*72 + c8] = *(const uint4*)&g_h2h[(m0 + r)*64 + c8];
    }
    #pragma unroll
    for (int ii = 0; ii < 16; ii++) {
        int idx = tid + 128*ii, r = idx >> 5, c4 = (idx & 31) * 4;
        float4 v = *(const float4*)&Wb[r*CDIM + n0 + c4];
        uint2 u; u.x = pack2(v.x, v.y); u.y = pack2(v.z, v.w);
        *(uint2*)&Wsm[r*136 + c4] = u;
    }
    __syncthreads();

    const unsigned hA = (unsigned)__cvta_generic_to_shared(Hs)
                      + (unsigned)(((w*16 + (lane & 15))*72 + (lane >> 4)*8) * 2);
    const unsigned wB = (unsigned)__cvta_generic_to_shared(Wsm)
                      + (unsigned)(((lane & 15)*136) * 2);

    float acc[16][4] = {};
    #pragma unroll
    for (int ks = 0; ks < 4; ks++) {
        const int kk = ks * 16;
        unsigned af[4];
        ldsm4(af[0], af[1], af[2], af[3], hA + (unsigned)(kk * 2));
        #pragma unroll
        for (int j = 0; j < 16; j++) {
            unsigned bf[2];
            ldsm2t(bf[0], bf[1], wB + (unsigned)((kk*136 + j*8) * 2));
            mma16(acc[j], af, bf);
        }
    }

    const int rA = w*16 + (lane >> 2);
    #pragma unroll
    for (int j = 0; j < 16; j++) {
        int n = n0 + j*8 + (lane & 3)*2;
        float2 bv = *(const float2*)&bias[n];
        size_t b0 = (size_t)(m0 + rA    )*CDIM + n;
        size_t b1 = (size_t)(m0 + rA + 8)*CDIM + n;
        *(float2*)&out[b0] = make_float2(acc[j][0] + bv.x, acc[j][1] + bv.y);
        *(float2*)&out[b1] = make_float2(acc[j][2] + bv.x, acc[j][3] + bv.y);
    }
}

// ---------------------------------------------------------------------------
// Flash attention, fp16 mma.m16n8k16, fp32 accum, exp2-domain softmax
// (ex2.approx.f16x2, packed-half2 max shuffles).
// Grid (NSEQ/128, B*H), 128 threads (4 warps), warp w owns q-rows [32w,32w+32).
// KV tile 64, THREE-buffer cp.async ring with ONE barrier per iteration:
// prefetch of tile t+2 is issued after the iter-t barrier, targeting the
// buffer last read in iter t-1 (all warps provably past it). Warps may drift
// a full iteration, overlapping softmax with neighbor warps' mma streams.
// ---------------------------------------------------------------------------
#define LDH 72
#define FLASH_SMEM ((128 + 3*128) * LDH * 2)

__global__ __launch_bounds__(128) void flash_mma_kernel()
{
    extern __shared__ __align__(16) __half smh[];
    __half* Qs = smh;                                 // [128][LDH]

    const int tid  = threadIdx.x;
    const int lane = tid & 31, w = tid >> 5;
    const int bh = blockIdx.y;
    const int q0 = blockIdx.x * 128;
    const int b = bh >> 4, h = bh & 15;

    const __half* Qg  = g_qh  + ((size_t)bh * NSEQ + q0) * DH;
    const __half* Kg  = g_kh  + (size_t)bh * NSEQ * DH;
    const __half* VTg = g_vTh + (size_t)bh * DH * NSEQ;

    const unsigned sbase = (unsigned)__cvta_generic_to_shared(smh);

    // prologue: async-load KV tiles 0 and 1 into bufs 0 and 1
    #pragma unroll
    for (int pb = 0; pb < 2; pb++) {
        const __half* Kt = Kg + (size_t)pb * 64 * DH;
        unsigned kdst = sbase + (unsigned)((128 + pb*128)*LDH*2);
        unsigned vdst = kdst + (unsigned)(64*LDH*2);
        #pragma unroll
        for (int it = 0; it < 4; it++) {
            int i = tid + 128*it, r = i >> 3, c8 = (i & 7)*8;
            cp16(kdst + (unsigned)((r*LDH + c8)*2), &Kt[r*DH + c8]);
            cp16(vdst + (unsigned)((r*LDH + c8)*2), &VTg[(size_t)r*NSEQ + pb*64 + c8]);
        }
        cp_commit();
    }
    // Q tile to SMEM, then hoist fragments to registers
    #pragma unroll
    for (int it = 0; it < 8; it++) {
        int i = tid + 128 * it, r = i >> 3, c8 = (i & 7) * 8;
        *(uint4*)&Qs[r*LDH + c8] = *(const uint4*)&Qg[r*DH + c8];
    }
    __syncthreads();

    const unsigned aOff = (unsigned)((((lane & 15) * LDH) + (lane >> 4) * 8) * 2);
    const unsigned bOff = (unsigned)((((lane & 7) * LDH) + ((lane >> 3) & 1) * 8) * 2);

    unsigned qf[2][4][4];      // [m-tile][k-step][frag]
    #pragma unroll
    for (int mt = 0; mt < 2; mt++)
        #pragma unroll
        for (int ks = 0; ks < 4; ks++)
            ldsm4(qf[mt][ks][0], qf[mt][ks][1], qf[mt][ks][2], qf[mt][ks][3],
                  sbase + aOff + (unsigned)(((w*32 + mt*16)*LDH + ks*16) * 2));

    float o[2][8][4];
    float mrow[2][2], lrow[2][2];     // lrow = per-thread PARTIAL row sums
    #pragma unroll
    for (int mt = 0; mt < 2; mt++) {
        mrow[mt][0] = mrow[mt][1] = -1e30f;
        lrow[mt][0] = lrow[mt][1] = 0.f;
        #pragma unroll
        for (int j = 0; j < 8; j++)
            o[mt][j][0] = o[mt][j][1] = o[mt][j][2] = o[mt][j][3] = 0.f;
    }

    int buf = 0;                      // t % 3 without a modulo each iter
    for (int t = 0; t < NSEQ/64; t++) {
        if (t + 1 < NSEQ/64) cp_wait<1>(); else cp_wait<0>();
        __syncthreads();              // the ONLY barrier in the loop

        // prefetch tile t+2 into the buffer last read at iter t-1 (safe now)
        if (t + 2 < NSEQ/64) {
            int pb = buf + 2; if (pb >= 3) pb -= 3;
            const __half* Kt = Kg + (size_t)(t+2) * 64 * DH;
            unsigned kdst = sbase + (unsigned)((128 + pb*128)*LDH*2);
            unsigned vdst = kdst + (unsigned)(64*LDH*2);
            #pragma unroll
            for (int it = 0; it < 4; it++) {
                int i = tid + 128*it, r = i >> 3, c8 = (i & 7)*8;
                cp16(kdst + (unsigned)((r*LDH + c8)*2), &Kt[r*DH + c8]);
                cp16(vdst + (unsigned)((r*LDH + c8)*2), &VTg[(size_t)r*NSEQ + (t+2)*64 + c8]);
            }
            cp_commit();
        }

        const unsigned kB = sbase + (unsigned)((128 + buf*128)*LDH*2) + bOff;
        const unsigned vB = kB + (unsigned)(64*LDH*2);

        // ---- S = Q K^T  (Q from registers; per warp 2 m-tiles x 8 n-tiles) ----
        float s[2][8][4];
        #pragma unroll
        for (int mt = 0; mt < 2; mt++)
            #pragma unroll
            for (int j = 0; j < 8; j++)
                s[mt][j][0] = s[mt][j][1] = s[mt][j][2] = s[mt][j][3] = 0.f;

        #pragma unroll
        for (int ks = 0; ks < 4; ks++) {
            const int kk = ks * 16;
            unsigned bf[8][2];
            #pragma unroll
            for (int j = 0; j < 8; j++)
                ldsm2(bf[j][0], bf[j][1], kB + (unsigned)((j*8*LDH + kk) * 2));
            #pragma unroll
            for (int mt = 0; mt < 2; mt++)
                #pragma unroll
                for (int j = 0; j < 8; j++) mma16(s[mt][j], qf[mt][ks], bf[j]);
        }

        // ---- per m-tile: softmax (f16x2 ex2, packed max shfl) then PV ----
        #pragma unroll
        for (int mt = 0; mt < 2; mt++) {
            float mxl = -1e30f, mxh = -1e30f;
            #pragma unroll
            for (int j = 0; j < 8; j++) {
                mxl = fmaxf(mxl, fmaxf(s[mt][j][0], s[mt][j][1]));
                mxh = fmaxf(mxh, fmaxf(s[mt][j][2], s[mt][j][3]));
            }
            // packed half2 quad-max (fp16-rounded max is safe: only shifts d by <=ulp)
            __half2 m2 = __floats2half2_rn(mxl, mxh);
            unsigned mu = *(unsigned*)&m2;
            unsigned s1 = __shfl_xor_sync(0xffffffffu, mu, 1);
            m2 = __hmax2(m2, *(__half2*)&s1);
            mu = *(unsigned*)&m2;
            unsigned s2 = __shfl_xor_sync(0xffffffffu, mu, 2);
            m2 = __hmax2(m2, *(__half2*)&s2);
            float2 mf = __half22float2(m2);

            float mln = fmaxf(mrow[mt][0], mf.x);
            float mhn = fmaxf(mrow[mt][1], mf.y);
            float al = exp2f(mrow[mt][0] - mln);
            float ah = exp2f(mrow[mt][1] - mhn);
            bool resc = (mln > mrow[mt][0]) | (mhn > mrow[mt][1]);
            mrow[mt][0] = mln; mrow[mt][1] = mhn;

            unsigned pp[8][2];
            float sl = 0.f, sh = 0.f;
            #pragma unroll
            for (int j = 0; j < 8; j++) {
                unsigned hl = ex2_h2(pack2(s[mt][j][0] - mln, s[mt][j][1] - mln));
                unsigned hh = ex2_h2(pack2(s[mt][j][2] - mhn, s[mt][j][3] - mhn));
                float2 fl = __half22float2(*(__half2*)&hl);
                float2 fh = __half22float2(*(__half2*)&hh);
                sl += fl.x + fl.y; sh += fh.x + fh.y;
                pp[j][0] = hl;
                pp[j][1] = hh;
            }
            lrow[mt][0] = lrow[mt][0]*al + sl;   // al/ah == 1 when no rescale
            lrow[mt][1] = lrow[mt][1]*ah + sh;
            if (__any_sync(0xffffffffu, resc)) {
                #pragma unroll
                for (int j = 0; j < 8; j++) {
                    o[mt][j][0] *= al; o[mt][j][1] *= al;
                    o[mt][j][2] *= ah; o[mt][j][3] *= ah;
                }
            }

            // O[mt] += P[mt] V
            #pragma unroll
            for (int ks = 0; ks < 4; ks++) {
                const int kc = ks * 16;
                unsigned af[4] = { pp[2*ks][0], pp[2*ks][1],
                                   pp[2*ks+1][0], pp[2*ks+1][1] };
                #pragma unroll
                for (int jd = 0; jd < 8; jd++) {
                    unsigned bf[2];
                    ldsm2(bf[0], bf[1], vB + (unsigned)((jd*8*LDH + kc) * 2));
                    mma16(o[mt][jd], af, bf);
                }
            }
        }
        // no trailing barrier: 3-buffer ring + top-of-loop barrier make it safe
        if (++buf == 3) buf = 0;
    }

    // ---- epilogue: quad-reduce partial sums, fp16 out to g_attnh ----
    #pragma unroll
    for (int mt = 0; mt < 2; mt++) {
        lrow[mt][0] += __shfl_xor_sync(0xffffffffu, lrow[mt][0], 1);
        lrow[mt][0] += __shfl_xor_sync(0xffffffffu, lrow[mt][0], 2);
        lrow[mt][1] += __shfl_xor_sync(0xffffffffu, lrow[mt][1], 1);
        lrow[mt][1] += __shfl_xor_sync(0xffffffffu, lrow[mt][1], 2);
        float il = 1.0f / lrow[mt][0], ih = 1.0f / lrow[mt][1];
        int rowl = q0 + w*32 + mt*16 + (lane >> 2);
        size_t basel = ((size_t)(b*NSEQ + rowl))*CDIM + h*DH + (lane & 3)*2;
        size_t baseh = basel + (size_t)8*CDIM;
        #pragma unroll
        for (int j = 0; j < 8; j++) {
            *(unsigned*)&g_attnh[basel + j*8] = pack2(o[mt][j][0]*il, o[mt][j][1]*il);
            *(unsigned*)&g_attnh[baseh + j*8] = pack2(o[mt][j][2]*ih, o[mt][j][3]*ih);
        }
    }
}

// ---------------------------------------------------------------------------
extern "C" void kernel_launch(void* const* d_in, const int* in_sizes, int n_in,
                              void* d_out, int out_size)
{
    const float* x        = (const float*)d_in[0];
    const float* w_qkv_a  = (const float*)d_in[1];
    const float* w_qkv_b  = (const float*)d_in[2];
    const float* w_proj_a = (const float*)d_in[3];
    const float* b_proj_a = (const float*)d_in[4];
    const float* w_proj_b = (const float*)d_in[5];
    const float* b_proj_b = (const float*)d_in[6];
    float* out = (float*)d_out;

    __half *pwah = nullptr, *phh = nullptr, *ph2h = nullptr, *pattnh = nullptr;
    cudaGetSymbolAddress((void**)&pwah,   g_wah);
    cudaGetSymbolAddress((void**)&phh,    g_hh);
    cudaGetSymbolAddress((void**)&ph2h,   g_h2h);
    cudaGetSymbolAddress((void**)&pattnh, g_attnh);

    static bool attr_set = false;
    if (!attr_set) {
        cudaFuncSetAttribute(flash_mma_kernel,
                             cudaFuncAttributeMaxDynamicSharedMemorySize, FLASH_SMEM);
        attr_set = true;
    }

    // 0. fp16 weight staging for the two K=1024 "A" GEMMs
    convert_w_kernel<<<64, 256>>>(w_qkv_a, w_proj_a);
    // 1. h = gelu(x @ w_qkv_a)                 fp16 [4096,64]
    lowrank_a_mma_kernel<false><<<MTOT/32, 64>>>(x, nullptr, pwah, nullptr, phh);
    // 2. qkv = h @ w_qkv_b (mma) -> q (x0.125*log2e), k, vT  (fp16)
    expand_mma_kernel<<<dim3(3*CDIM/128, MTOT/64), 128>>>(w_qkv_b);
    // 3. fp16 tensor-core flash attention -> g_attnh [B,N,C] fp16
    flash_mma_kernel<<<dim3(NSEQ/128, BD*HEADS), 128, FLASH_SMEM>>>();
    // 4. h2 = gelu(attn @ w_proj_a + b_proj_a) fp16 [4096,64]
    lowrank_a_mma_kernel<true><<<MTOT/32, 64>>>(nullptr, pattnh, pwah + KDIM*RANK,
                                                b_proj_a, ph2h);
    // 5. y = h2 @ w_proj_b + b_proj_b (mma)    fp32 [4096,1024]
    lowrank_out_mma_kernel<<<dim3(CDIM/128, MTOT/64), 128>>>(w_proj_b, b_proj_b, out);
}

// round 17
// speedup vs baseline: 1.1688x; 1.0371x over previous
#include <cuda_runtime.h>
#include <cuda_fp16.h>
#include <math.h>

#define BD    2
#define NSEQ  2048
#define CDIM  1024
#define RANK  64
#define HEADS 16
#define DH    64
#define MTOT  (BD*NSEQ)   // 4096
#define KDIM  1024

// Scratch (device globals: no allocation allowed in kernel_launch)
__device__ __half g_wah [2*KDIM*RANK];          // fp16 w_qkv_a | w_proj_a
__device__ __half g_hh  [MTOT*RANK];            // gelu(x @ w_qkv_a), fp16
__device__ __half g_h2h [MTOT*RANK];            // gelu(attn @ w_proj_a + b), fp16
__device__ __half g_qh  [BD*HEADS*NSEQ*DH];     // Q * 0.125*log2e, fp16 [bh][n][d]
__device__ __half g_kh  [BD*HEADS*NSEQ*DH];     // K fp16               [bh][n][d]
__device__ __half g_vTh [BD*HEADS*DH*NSEQ];     // V^T fp16             [bh][d][n]
__device__ __half g_attnh[MTOT*CDIM];           // attention out [B,N,C] fp16

__device__ __forceinline__ float gelu_exact(float v) {
    return 0.5f * v * (1.0f + erff(v * 0.70710678118654752440f));
}
__device__ __forceinline__ unsigned pack2(float a, float b) {
    __half2 h = __floats2half2_rn(a, b);
    return *(unsigned*)&h;
}
__device__ __forceinline__ unsigned ex2_h2(unsigned d) {
    unsigned r;
    asm("ex2.approx.f16x2 %0, %1;" : "=r"(r) : "r"(d));
    return r;
}
__device__ __forceinline__ void ldsm4(unsigned &r0, unsigned &r1, unsigned &r2, unsigned &r3, unsigned a) {
    asm volatile("ldmatrix.sync.aligned.m8n8.x4.shared.b16 {%0,%1,%2,%3}, [%4];"
                 : "=r"(r0),"=r"(r1),"=r"(r2),"=r"(r3) : "r"(a));
}
__device__ __forceinline__ void ldsm2(unsigned &r0, unsigned &r1, unsigned a) {
    asm volatile("ldmatrix.sync.aligned.m8n8.x2.shared.b16 {%0,%1}, [%2];"
                 : "=r"(r0),"=r"(r1) : "r"(a));
}
__device__ __forceinline__ void ldsm2t(unsigned &r0, unsigned &r1, unsigned a) {
    asm volatile("ldmatrix.sync.aligned.m8n8.x2.trans.shared.b16 {%0,%1}, [%2];"
                 : "=r"(r0),"=r"(r1) : "r"(a));
}
__device__ __forceinline__ void mma16(float* c, const unsigned* a, const unsigned* b) {
    asm volatile("mma.sync.aligned.m16n8k16.row.col.f32.f16.f16.f32 "
                 "{%0,%1,%2,%3},{%4,%5,%6,%7},{%8,%9},{%0,%1,%2,%3};"
                 : "+f"(c[0]),"+f"(c[1]),"+f"(c[2]),"+f"(c[3])
                 : "r"(a[0]),"r"(a[1]),"r"(a[2]),"r"(a[3]),"r"(b[0]),"r"(b[1]));
}
__device__ __forceinline__ void cp16(unsigned dst, const void* src) {
    asm volatile("cp.async.cg.shared.global [%0], [%1], 16;" :: "r"(dst), "l"(src));
}
__device__ __forceinline__ void cp_commit() { asm volatile("cp.async.commit_group;"); }
template<int N> __device__ __forceinline__ void cp_wait() {
    asm volatile("cp.async.wait_group %0;" :: "n"(N));
}
__device__ __forceinline__ void barhalf(int id) {
    asm volatile("bar.sync %0, 64;" :: "r"(id) : "memory");
}

// ---------------------------------------------------------------------------
// One-shot weight converter: w_qkv_a, w_proj_a (fp32 [1024][64]) -> g_wah fp16.
// ---------------------------------------------------------------------------
__global__ __launch_bounds__(256) void convert_w_kernel(
    const float* __restrict__ wa, const float* __restrict__ wpa)
{
    int idx = blockIdx.x * 256 + threadIdx.x;
    float4 a = *(const float4*)&wa[idx * 4];
    float4 b = *(const float4*)&wpa[idx * 4];
    uint2 ua; ua.x = pack2(a.x, a.y); ua.y = pack2(a.z, a.w);
    uint2 ub; ub.x = pack2(b.x, b.y); ub.y = pack2(b.z, b.w);
    *(uint2*)&g_wah[idx * 4]               = ua;
    *(uint2*)&g_wah[KDIM*RANK + idx * 4]   = ub;
}

// ---------------------------------------------------------------------------
// out_fp16[M,64] = gelu(X[M,1024] @ W[1024,64] (+ bias)) via fp16 mma.
// K-SPLIT x2: 128 threads; warps {0,1} process K[0,512), warps {2,3} K[512,1024)
// concurrently (separate SMEM tiles + per-half named barriers). Serial chunk
// chain halves 16 -> 8. fp32 combine through SMEM, then gelu.
// ---------------------------------------------------------------------------
template<bool XH>
__global__ __launch_bounds__(128) void lowrank_a_mma_kernel(
    const float* __restrict__ Xf, const __half* __restrict__ Xh,
    const __half* __restrict__ Wh, const float* __restrict__ bias,
    __half* __restrict__ out)
{
    __shared__ __align__(16) __half Xs[2][32*72];
    __shared__ __align__(16) __half Ws[2][64*72];
    __shared__ __align__(16) float  Racc[32*66];
    const int tid = threadIdx.x;
    const int lane = tid & 31;
    const int half = tid >> 6;          // 0 or 1 (k-split half)
    const int hL   = tid & 63;          // thread id within half
    const int wl   = (tid >> 5) & 1;    // warp within half
    const int m0 = blockIdx.x * 32;
    const int kbase = half * (KDIM/2);

    float4 xreg[8];
    uint4  xreg16[4];
    uint4  wreg[8];

    if (XH) {
        #pragma unroll
        for (int ii = 0; ii < 4; ii++) {
            int idx = hL + 64*ii, r = idx >> 3, c8 = (idx & 7) * 8;
            xreg16[ii] = *(const uint4*)&Xh[(m0 + r)*KDIM + kbase + c8];
        }
    } else {
        #pragma unroll
        for (int ii = 0; ii < 8; ii++) {
            int idx = hL + 64*ii, r = idx >> 4, c4 = (idx & 15) * 4;
            xreg[ii] = *(const float4*)&Xf[(m0 + r)*KDIM + kbase + c4];
        }
    }
    #pragma unroll
    for (int ii = 0; ii < 8; ii++) {
        int idx = hL + 64*ii, r = idx >> 3, c8 = (idx & 7) * 8;
        wreg[ii] = *(const uint4*)&Wh[(kbase + r)*RANK + c8];
    }

    const unsigned hA = (unsigned)__cvta_generic_to_shared(&Xs[half][0])
                      + (unsigned)(((wl*16 + (lane & 15))*72 + (lane >> 4)*8) * 2);
    const unsigned wB = (unsigned)__cvta_generic_to_shared(&Ws[half][0])
                      + (unsigned)(((lane & 15)*72) * 2);

    float acc[8][4] = {};
    #pragma unroll 1
    for (int ch = 0; ch < KDIM/128; ch++) {       // 8 chunks per half
        if (XH) {
            #pragma unroll
            for (int ii = 0; ii < 4; ii++) {
                int idx = hL + 64*ii, r = idx >> 3, c8 = (idx & 7) * 8;
                *(uint4*)&Xs[half][r*72 + c8] = xreg16[ii];
            }
        } else {
            #pragma unroll
            for (int ii = 0; ii < 8; ii++) {
                int idx = hL + 64*ii, r = idx >> 4, c4 = (idx & 15) * 4;
                uint2 u; u.x = pack2(xreg[ii].x, xreg[ii].y);
                u.y = pack2(xreg[ii].z, xreg[ii].w);
                *(uint2*)&Xs[half][r*72 + c4] = u;
            }
        }
        #pragma unroll
        for (int ii = 0; ii < 8; ii++) {
            int idx = hL + 64*ii, r = idx >> 3, c8 = (idx & 7) * 8;
            *(uint4*)&Ws[half][r*72 + c8] = wreg[ii];
        }
        barhalf(1 + half);
        if (ch + 1 < KDIM/128) {
            const int k0 = kbase + (ch + 1) * 64;
            if (XH) {
                #pragma unroll
                for (int ii = 0; ii < 4; ii++) {
                    int idx = hL + 64*ii, r = idx >> 3, c8 = (idx & 7) * 8;
                    xreg16[ii] = *(const uint4*)&Xh[(m0 + r)*KDIM + k0 + c8];
                }
            } else {
                #pragma unroll
                for (int ii = 0; ii < 8; ii++) {
                    int idx = hL + 64*ii, r = idx >> 4, c4 = (idx & 15) * 4;
                    xreg[ii] = *(const float4*)&Xf[(m0 + r)*KDIM + k0 + c4];
                }
            }
            #pragma unroll
            for (int ii = 0; ii < 8; ii++) {
                int idx = hL + 64*ii, r = idx >> 3, c8 = (idx & 7) * 8;
                wreg[ii] = *(const uint4*)&Wh[(k0 + r)*RANK + c8];
            }
        }
        #pragma unroll
        for (int ks = 0; ks < 4; ks++) {
            const int kk = ks * 16;
            unsigned af[4];
            ldsm4(af[0], af[1], af[2], af[3], hA + (unsigned)(kk * 2));
            #pragma unroll
            for (int j = 0; j < 8; j++) {
                unsigned bf[2];
                ldsm2t(bf[0], bf[1], wB + (unsigned)((kk*72 + j*8) * 2));
                mma16(acc[j], af, bf);
            }
        }
        barhalf(1 + half);
    }

    // combine halves: half 1 publishes fp32 partials, half 0 adds + gelu + store
    const int rA = wl*16 + (lane >> 2);
    const int nc = (lane & 3)*2;
    if (half == 1) {
        #pragma unroll
        for (int j = 0; j < 8; j++) {
            *(float2*)&Racc[(rA    )*66 + j*8 + nc] = make_float2(acc[j][0], acc[j][1]);
            *(float2*)&Racc[(rA + 8)*66 + j*8 + nc] = make_float2(acc[j][2], acc[j][3]);
        }
    }
    __syncthreads();
    if (half == 0) {
        #pragma unroll
        for (int j = 0; j < 8; j++) {
            int n = j*8 + nc;
            float2 p0 = *(const float2*)&Racc[(rA    )*66 + n];
            float2 p1 = *(const float2*)&Racc[(rA + 8)*66 + n];
            float b0 = 0.f, b1 = 0.f;
            if (bias) { float2 bv = *(const float2*)&bias[n]; b0 = bv.x; b1 = bv.y; }
            *(unsigned*)&out[(m0 + rA    )*RANK + n] =
                pack2(gelu_exact(acc[j][0] + p0.x + b0), gelu_exact(acc[j][1] + p0.y + b1));
            *(unsigned*)&out[(m0 + rA + 8)*RANK + n] =
                pack2(gelu_exact(acc[j][2] + p1.x + b0), gelu_exact(acc[j][3] + p1.y + b1));
        }
    }
}

// ---------------------------------------------------------------------------
// qkv = g_hh[4096,64] @ w_qkv_b[64,3072] via fp16 mma ->
//   g_qh (x 0.125*log2e), g_kh, g_vTh (transposed via SMEM staging).
// ---------------------------------------------------------------------------
__global__ __launch_bounds__(128) void expand_mma_kernel(const float* __restrict__ Wb)
{
    __shared__ __align__(16) __half Hs[64*72];
    __shared__ __align__(16) __half Wsm[64*136];
    const int tid = threadIdx.x, lane = tid & 31, w = tid >> 5;
    const int n0 = blockIdx.x * 128;
    const int m0 = blockIdx.y * 64;

    #pragma unroll
    for (int ii = 0; ii < 4; ii++) {
        int idx = tid + 128*ii, r = idx >> 3, c8 = (idx & 7) * 8;
        *(uint4*)&Hs[r*72 + c8] = *(const uint4*)&g_hh[(m0 + r)*64 + c8];
    }
    #pragma unroll
    for (int ii = 0; ii < 16; ii++) {
        int idx = tid + 128*ii, r = idx >> 5, c4 = (idx & 31) * 4;
        float4 v = *(const float4*)&Wb[r*(3*CDIM) + n0 + c4];
        uint2 u; u.x = pack2(v.x, v.y); u.y = pack2(v.z, v.w);
        *(uint2*)&Wsm[r*136 + c4] = u;
    }
    __syncthreads();

    const unsigned hA = (unsigned)__cvta_generic_to_shared(Hs)
                      + (unsigned)(((w*16 + (lane & 15))*72 + (lane >> 4)*8) * 2);
    const unsigned wB = (unsigned)__cvta_generic_to_shared(Wsm)
                      + (unsigned)(((lane & 15)*136) * 2);

    float acc[16][4] = {};
    #pragma unroll
    for (int ks = 0; ks < 4; ks++) {
        const int kk = ks * 16;
        unsigned af[4];
        ldsm4(af[0], af[1], af[2], af[3], hA + (unsigned)(kk * 2));
        #pragma unroll
        for (int j = 0; j < 16; j++) {
            unsigned bf[2];
            ldsm2t(bf[0], bf[1], wB + (unsigned)((kk*136 + j*8) * 2));
            mma16(acc[j], af, bf);
        }
    }

    const int comp = n0 >> 10;
    const int bb   = m0 >> 11;
    const int ns0  = m0 & 2047;
    const int rA   = w*16 + (lane >> 2);

    if (comp < 2) {
        const float sc = (comp == 0) ? (0.125f * 1.44269504088896341f) : 1.0f;
        __half* dst = (comp == 0) ? g_qh : g_kh;
        #pragma unroll
        for (int j = 0; j < 16; j++) {
            int gn   = (n0 + j*8 + (lane & 3)*2) & 1023;
            int head = gn >> 6, d = gn & 63;
            size_t base = ((size_t)(bb*HEADS + head)*NSEQ + ns0);
            *(unsigned*)&dst[(base + rA    )*DH + d] = pack2(acc[j][0]*sc, acc[j][1]*sc);
            *(unsigned*)&dst[(base + rA + 8)*DH + d] = pack2(acc[j][2]*sc, acc[j][3]*sc);
        }
    } else {
        __syncthreads();
        __half* Ts = Hs;
        #pragma unroll
        for (int j = 0; j < 16; j++) {
            int c = j*8 + (lane & 3)*2;
            Ts[(c+0)*72 + rA    ] = __float2half(acc[j][0]);
            Ts[(c+1)*72 + rA    ] = __float2half(acc[j][1]);
            Ts[(c+0)*72 + rA + 8] = __float2half(acc[j][2]);
            Ts[(c+1)*72 + rA + 8] = __float2half(acc[j][3]);
        }
        __syncthreads();
        int c    = tid;
        int gn   = (n0 + c) & 1023;
        int head = gn >> 6, d = gn & 63;
        size_t base = ((size_t)(bb*HEADS + head)*DH + d)*NSEQ + ns0;
        #pragma unroll
        for (int g = 0; g < 8; g++)
            *(uint4*)&g_vTh[base + g*8] = *(uint4*)&Ts[c*72 + g*8];
    }
}

// ---------------------------------------------------------------------------
// y[4096,1024] = g_h2h[4096,64] @ w_proj_b[64,1024] + b_proj_b   (fp16 mma)
// ---------------------------------------------------------------------------
__global__ __launch_bounds__(128) void lowrank_out_mma_kernel(
    const float* __restrict__ Wb, const float* __restrict__ bias,
    float* __restrict__ out)
{
    __shared__ __align__(16) __half Hs[64*72];
    __shared__ __align__(16) __half Wsm[64*136];
    const int tid = threadIdx.x, lane = tid & 31, w = tid >> 5;
    const int n0 = blockIdx.x * 128;
    const int m0 = blockIdx.y * 64;

    #pragma unroll
    for (int ii = 0; ii < 4; ii++) {
        int idx = tid + 128*ii, r = idx >> 3, c8 = (idx & 7) * 8;
        *(uint4*)&Hs[r*72 + c8] = *(const uint4*)&g_h2h[(m0 + r)*64 + c8];
    }
    #pragma unroll
    for (int ii = 0; ii < 16; ii++) {
        int idx = tid + 128*ii, r = idx >> 5, c4 = (idx & 31) * 4;
        float4 v = *(const float4*)&Wb[r*CDIM + n0 + c4];
        uint2 u; u.x = pack2(v.x, v.y); u.y = pack2(v.z, v.w);
        *(uint2*)&Wsm[r*136 + c4] = u;
    }
    __syncthreads();

    const unsigned hA = (unsigned)__cvta_generic_to_shared(Hs)
                      + (unsigned)(((w*16 + (lane & 15))*72 + (lane >> 4)*8) * 2);
    const unsigned wB = (unsigned)__cvta_generic_to_shared(Wsm)
                      + (unsigned)(((lane & 15)*136) * 2);

    float acc[16][4] = {};
    #pragma unroll
    for (int ks = 0; ks < 4; ks++) {
        const int kk = ks * 16;
        unsigned af[4];
        ldsm4(af[0], af[1], af[2], af[3], hA + (unsigned)(kk * 2));
        #pragma unroll
        for (int j = 0; j < 16; j++) {
            unsigned bf[2];
            ldsm2t(bf[0], bf[1], wB + (unsigned)((kk*136 + j*8) * 2));
            mma16(acc[j], af, bf);
        }
    }

    const int rA = w*16 + (lane >> 2);
    #pragma unroll
    for (int j = 0; j < 16; j++) {
        int n = n0 + j*8 + (lane & 3)*2;
        float2 bv = *(const float2*)&bias[n];
        size_t b0 = (size_t)(m0 + rA    )*CDIM + n;
        size_t b1 = (size_t)(m0 + rA + 8)*CDIM + n;
        *(float2*)&out[b0] = make_float2(acc[j][0] + bv.x, acc[j][1] + bv.y);
        *(float2*)&out[b1] = make_float2(acc[j][2] + bv.x, acc[j][3] + bv.y);
    }
}

// ---------------------------------------------------------------------------
// Flash attention, fp16 mma.m16n8k16, fp32 accum, exp2-domain softmax
// (ex2.approx.f16x2, packed-half2 max shuffles). Unchanged from R16 best.
// 3-buffer cp.async ring, ONE barrier per iteration, Q fragments in regs,
// P in registers, deferred l-reduction + conditional O rescale.
// ---------------------------------------------------------------------------
#define LDH 72
#define FLASH_SMEM ((128 + 3*128) * LDH * 2)

__global__ __launch_bounds__(128) void flash_mma_kernel()
{
    extern __shared__ __align__(16) __half smh[];
    __half* Qs = smh;                                 // [128][LDH]

    const int tid  = threadIdx.x;
    const int lane = tid & 31, w = tid >> 5;
    const int bh = blockIdx.y;
    const int q0 = blockIdx.x * 128;
    const int b = bh >> 4, h = bh & 15;

    const __half* Qg  = g_qh  + ((size_t)bh * NSEQ + q0) * DH;
    const __half* Kg  = g_kh  + (size_t)bh * NSEQ * DH;
    const __half* VTg = g_vTh + (size_t)bh * DH * NSEQ;

    const unsigned sbase = (unsigned)__cvta_generic_to_shared(smh);

    #pragma unroll
    for (int pb = 0; pb < 2; pb++) {
        const __half* Kt = Kg + (size_t)pb * 64 * DH;
        unsigned kdst = sbase + (unsigned)((128 + pb*128)*LDH*2);
        unsigned vdst = kdst + (unsigned)(64*LDH*2);
        #pragma unroll
        for (int it = 0; it < 4; it++) {
            int i = tid + 128*it, r = i >> 3, c8 = (i & 7)*8;
            cp16(kdst + (unsigned)((r*LDH + c8)*2), &Kt[r*DH + c8]);
            cp16(vdst + (unsigned)((r*LDH + c8)*2), &VTg[(size_t)r*NSEQ + pb*64 + c8]);
        }
        cp_commit();
    }
    #pragma unroll
    for (int it = 0; it < 8; it++) {
        int i = tid + 128 * it, r = i >> 3, c8 = (i & 7) * 8;
        *(uint4*)&Qs[r*LDH + c8] = *(const uint4*)&Qg[r*DH + c8];
    }
    __syncthreads();

    const unsigned aOff = (unsigned)((((lane & 15) * LDH) + (lane >> 4) * 8) * 2);
    const unsigned bOff = (unsigned)((((lane & 7) * LDH) + ((lane >> 3) & 1) * 8) * 2);

    unsigned qf[2][4][4];
    #pragma unroll
    for (int mt = 0; mt < 2; mt++)
        #pragma unroll
        for (int ks = 0; ks < 4; ks++)
            ldsm4(qf[mt][ks][0], qf[mt][ks][1], qf[mt][ks][2], qf[mt][ks][3],
                  sbase + aOff + (unsigned)(((w*32 + mt*16)*LDH + ks*16) * 2));

    float o[2][8][4];
    float mrow[2][2], lrow[2][2];
    #pragma unroll
    for (int mt = 0; mt < 2; mt++) {
        mrow[mt][0] = mrow[mt][1] = -1e30f;
        lrow[mt][0] = lrow[mt][1] = 0.f;
        #pragma unroll
        for (int j = 0; j < 8; j++)
            o[mt][j][0] = o[mt][j][1] = o[mt][j][2] = o[mt][j][3] = 0.f;
    }

    int buf = 0;
    for (int t = 0; t < NSEQ/64; t++) {
        if (t + 1 < NSEQ/64) cp_wait<1>(); else cp_wait<0>();
        __syncthreads();

        if (t + 2 < NSEQ/64) {
            int pb = buf + 2; if (pb >= 3) pb -= 3;
            const __half* Kt = Kg + (size_t)(t+2) * 64 * DH;
            unsigned kdst = sbase + (unsigned)((128 + pb*128)*LDH*2);
            unsigned vdst = kdst + (unsigned)(64*LDH*2);
            #pragma unroll
            for (int it = 0; it < 4; it++) {
                int i = tid + 128*it, r = i >> 3, c8 = (i & 7)*8;
                cp16(kdst + (unsigned)((r*LDH + c8)*2), &Kt[r*DH + c8]);
                cp16(vdst + (unsigned)((r*LDH + c8)*2), &VTg[(size_t)r*NSEQ + (t+2)*64 + c8]);
            }
            cp_commit();
        }

        const unsigned kB = sbase + (unsigned)((128 + buf*128)*LDH*2) + bOff;
        const unsigned vB = kB + (unsigned)(64*LDH*2);

        float s[2][8][4];
        #pragma unroll
        for (int mt = 0; mt < 2; mt++)
            #pragma unroll
            for (int j = 0; j < 8; j++)
                s[mt][j][0] = s[mt][j][1] = s[mt][j][2] = s[mt][j][3] = 0.f;

        #pragma unroll
        for (int ks = 0; ks < 4; ks++) {
            const int kk = ks * 16;
            unsigned bf[8][2];
            #pragma unroll
            for (int j = 0; j < 8; j++)
                ldsm2(bf[j][0], bf[j][1], kB + (unsigned)((j*8*LDH + kk) * 2));
            #pragma unroll
            for (int mt = 0; mt < 2; mt++)
                #pragma unroll
                for (int j = 0; j < 8; j++) mma16(s[mt][j], qf[mt][ks], bf[j]);
        }

        #pragma unroll
        for (int mt = 0; mt < 2; mt++) {
            float mxl = -1e30f, mxh = -1e30f;
            #pragma unroll
            for (int j = 0; j < 8; j++) {
                mxl = fmaxf(mxl, fmaxf(s[mt][j][0], s[mt][j][1]));
                mxh = fmaxf(mxh, fmaxf(s[mt][j][2], s[mt][j][3]));
            }
            __half2 m2 = __floats2half2_rn(mxl, mxh);
            unsigned mu = *(unsigned*)&m2;
            unsigned s1 = __shfl_xor_sync(0xffffffffu, mu, 1);
            m2 = __hmax2(m2, *(__half2*)&s1);
            mu = *(unsigned*)&m2;
            unsigned s2 = __shfl_xor_sync(0xffffffffu, mu, 2);
            m2 = __hmax2(m2, *(__half2*)&s2);
            float2 mf = __half22float2(m2);

            float mln = fmaxf(mrow[mt][0], mf.x);
            float mhn = fmaxf(mrow[mt][1], mf.y);
            float al = exp2f(mrow[mt][0] - mln);
            float ah = exp2f(mrow[mt][1] - mhn);
            bool resc = (mln > mrow[mt][0]) | (mhn > mrow[mt][1]);
            mrow[mt][0] = mln; mrow[mt][1] = mhn;

            unsigned pp[8][2];
            float sl = 0.f, sh = 0.f;
            #pragma unroll
            for (int j = 0; j < 8; j++) {
                unsigned hl = ex2_h2(pack2(s[mt][j][0] - mln, s[mt][j][1] - mln));
                unsigned hh = ex2_h2(pack2(s[mt][j][2] - mhn, s[mt][j][3] - mhn));
                float2 fl = __half22float2(*(__half2*)&hl);
                float2 fh = __half22float2(*(__half2*)&hh);
                sl += fl.x + fl.y; sh += fh.x + fh.y;
                pp[j][0] = hl;
                pp[j][1] = hh;
            }
            lrow[mt][0] = lrow[mt][0]*al + sl;
            lrow[mt][1] = lrow[mt][1]*ah + sh;
            if (__any_sync(0xffffffffu, resc)) {
                #pragma unroll
                for (int j = 0; j < 8; j++) {
                    o[mt][j][0] *= al; o[mt][j][1] *= al;
                    o[mt][j][2] *= ah; o[mt][j][3] *= ah;
                }
            }

            #pragma unroll
            for (int ks = 0; ks < 4; ks++) {
                const int kc = ks * 16;
                unsigned af[4] = { pp[2*ks][0], pp[2*ks][1],
                                   pp[2*ks+1][0], pp[2*ks+1][1] };
                #pragma unroll
                for (int jd = 0; jd < 8; jd++) {
                    unsigned bf[2];
                    ldsm2(bf[0], bf[1], vB + (unsigned)((jd*8*LDH + kc) * 2));
                    mma16(o[mt][jd], af, bf);
                }
            }
        }
        if (++buf == 3) buf = 0;
    }

    #pragma unroll
    for (int mt = 0; mt < 2; mt++) {
        lrow[mt][0] += __shfl_xor_sync(0xffffffffu, lrow[mt][0], 1);
        lrow[mt][0] += __shfl_xor_sync(0xffffffffu, lrow[mt][0], 2);
        lrow[mt][1] += __shfl_xor_sync(0xffffffffu, lrow[mt][1], 1);
        lrow[mt][1] += __shfl_xor_sync(0xffffffffu, lrow[mt][1], 2);
        float il = 1.0f / lrow[mt][0], ih = 1.0f / lrow[mt][1];
        int rowl = q0 + w*32 + mt*16 + (lane >> 2);
        size_t basel = ((size_t)(b*NSEQ + rowl))*CDIM + h*DH + (lane & 3)*2;
        size_t baseh = basel + (size_t)8*CDIM;
        #pragma unroll
        for (int j = 0; j < 8; j++) {
            *(unsigned*)&g_attnh[basel + j*8] = pack2(o[mt][j][0]*il, o[mt][j][1]*il);
            *(unsigned*)&g_attnh[baseh + j*8] = pack2(o[mt][j][2]*ih, o[mt][j][3]*ih);
        }
    }
}

// ---------------------------------------------------------------------------
extern "C" void kernel_launch(void* const* d_in, const int* in_sizes, int n_in,
                              void* d_out, int out_size)
{
    const float* x        = (const float*)d_in[0];
    const float* w_qkv_a  = (const float*)d_in[1];
    const float* w_qkv_b  = (const float*)d_in[2];
    const float* w_proj_a = (const float*)d_in[3];
    const float* b_proj_a = (const float*)d_in[4];
    const float* w_proj_b = (const float*)d_in[5];
    const float* b_proj_b = (const float*)d_in[6];
    float* out = (float*)d_out;

    __half *pwah = nullptr, *phh = nullptr, *ph2h = nullptr, *pattnh = nullptr;
    cudaGetSymbolAddress((void**)&pwah,   g_wah);
    cudaGetSymbolAddress((void**)&phh,    g_hh);
    cudaGetSymbolAddress((void**)&ph2h,   g_h2h);
    cudaGetSymbolAddress((void**)&pattnh, g_attnh);

    static bool attr_set = false;
    if (!attr_set) {
        cudaFuncSetAttribute(flash_mma_kernel,
                             cudaFuncAttributeMaxDynamicSharedMemorySize, FLASH_SMEM);
        attr_set = true;
    }

    // 0. fp16 weight staging for the two K=1024 "A" GEMMs
    convert_w_kernel<<<64, 256>>>(w_qkv_a, w_proj_a);
    // 1. h = gelu(x @ w_qkv_a)                 fp16 [4096,64]  (k-split x2)
    lowrank_a_mma_kernel<false><<<MTOT/32, 128>>>(x, nullptr, pwah, nullptr, phh);
    // 2. qkv = h @ w_qkv_b (mma) -> q (x0.125*log2e), k, vT  (fp16)
    expand_mma_kernel<<<dim3(3*CDIM/128, MTOT/64), 128>>>(w_qkv_b);
    // 3. fp16 tensor-core flash attention -> g_attnh [B,N,C] fp16
    flash_mma_kernel<<<dim3(NSEQ/128, BD*HEADS), 128, FLASH_SMEM>>>();
    // 4. h2 = gelu(attn @ w_proj_a + b_proj_a) fp16 [4096,64]  (k-split x2)
    lowrank_a_mma_kernel<true><<<MTOT/32, 128>>>(nullptr, pattnh, pwah + KDIM*RANK,
                                                 b_proj_a, ph2h);
    // 5. y = h2 @ w_proj_b + b_proj_b (mma)    fp32 [4096,1024]
    lowrank_out_mma_kernel<<<dim3(CDIM/128, MTOT/64), 128>>>(w_proj_b, b_proj_b, out);
}